// round 3
// baseline (speedup 1.0000x reference)
#include <cuda_runtime.h>
#include <cuda_bf16.h>
#include <math.h>

#define Hx   24
#define Dx   128
#define NHx  4
#define DHx  32
#define FFx  512
#define RS32 0.17677669529663687f  /* 1/sqrt(32) */

// ---------------------------------------------------------------------------
// Precomputed batch-independent tables (device globals; recomputed per launch)
// ---------------------------------------------------------------------------
__device__ float g_E [2][3][Hx][Dx];      // Qe/Ke/Ve = fe @ W{q,k,v}^T
__device__ float g_G [2][NHx][Hx][Hx];    // (Qe_i . Ke_j)/sqrt(DH)
__device__ float g_Mk[2][NHx][Hx][Hx];    // mask bias + qb.kb/sqrt(DH), -1e30 invalid
__device__ float g_gq[2][NHx][Hx];
__device__ float g_gk[2][NHx][Hx];
__device__ float g_P [2][NHx*Hx][Dx];     // out_w (head slice) @ Ve
__device__ float g_Pc[2][Dx];             // out_b + out_w @ vb
__device__ float g_gw[2][Dx];             // ln2_g * op_w * alpha
__device__ float g_sc[2][2];              // [br][0]=sum(gw), [1]=alpha*(sum(ln2_b*op_w)+op_b)

// ---------------------------------------------------------------------------
// Precompute 1: Qe/Ke/Ve  (grid 6 = 2 branches x {q,k,v})
// ---------------------------------------------------------------------------
__global__ void pre_qkv(const float* __restrict__ fe,
                        const float* __restrict__ inwp,
                        const float* __restrict__ inwf) {
    int br = blockIdx.x / 3, which = blockIdx.x % 3;
    const float* W = (br ? inwf : inwp) + which * Dx * Dx;
    __shared__ float fes[Hx * Dx];
    for (int idx = threadIdx.x; idx < Hx * Dx; idx += blockDim.x) fes[idx] = fe[idx];
    __syncthreads();
    for (int idx = threadIdx.x; idx < Hx * Dx; idx += blockDim.x) {
        int i = idx >> 7, c = idx & 127;
        float s = 0.f;
        #pragma unroll 8
        for (int d = 0; d < Dx; d++) s += fes[i * Dx + d] * W[c * Dx + d];
        g_E[br][which][i][c] = s;
    }
}

// ---------------------------------------------------------------------------
// Precompute 2: G, Mk, gq, gk, P, Pc, gw, scalars  (grid 2 = branches)
// ---------------------------------------------------------------------------
__global__ void pre_misc(const float* __restrict__ inbp, const float* __restrict__ inbf,
                         const float* __restrict__ outwp, const float* __restrict__ outbp,
                         const float* __restrict__ outwf, const float* __restrict__ outbf,
                         const float* __restrict__ ln2g, const float* __restrict__ ln2b,
                         const float* __restrict__ oppw, const float* __restrict__ oppb,
                         const float* __restrict__ opfw, const float* __restrict__ opfb,
                         const float* __restrict__ alog,
                         const float* __restrict__ biasp, const float* __restrict__ biasf) {
    int br = blockIdx.x;
    const float* inb  = br ? inbf  : inbp;
    const float* outw = br ? outwf : outwp;
    const float* outb = br ? outbf : outbp;
    const float* opw  = br ? opfw  : oppw;
    const float* opb  = br ? opfb  : oppb;
    const float* bias = br ? biasf : biasp;
    const float* qb = inb, *kb = inb + Dx, *vb = inb + 2 * Dx;
    __shared__ float g0s[NHx];
    int tid = threadIdx.x;
    if (tid < NHx) {
        float s = 0.f;
        for (int d = 0; d < DHx; d++) s += qb[tid * DHx + d] * kb[tid * DHx + d];
        g0s[tid] = s * RS32;
    }
    __syncthreads();
    for (int idx = tid; idx < NHx * Hx; idx += blockDim.x) {
        int n = idx / Hx, i = idx % Hx;
        float s1 = 0.f, s2 = 0.f;
        for (int d = 0; d < DHx; d++) {
            s1 += g_E[br][0][i][n * DHx + d] * kb[n * DHx + d];
            s2 += g_E[br][1][i][n * DHx + d] * qb[n * DHx + d];
        }
        g_gq[br][n][i] = s1 * RS32;
        g_gk[br][n][i] = s2 * RS32;
    }
    for (int idx = tid; idx < NHx * Hx * Hx; idx += blockDim.x) {
        int n = idx / (Hx * Hx), i = (idx / Hx) % Hx, j = idx % Hx;
        float s = 0.f;
        for (int d = 0; d < DHx; d++)
            s += g_E[br][0][i][n * DHx + d] * g_E[br][1][j][n * DHx + d];
        g_G[br][n][i][j] = s * RS32;
        bool valid = (br == 0) ? (j <= i) : (j >= i);
        g_Mk[br][n][i][j] = valid ? bias[j - i + Hx - 1] + g0s[n] : -1e30f;
    }
    for (int idx = tid; idx < NHx * Hx * Dx; idx += blockDim.x) {
        int k = idx >> 7, c = idx & 127;
        int n = k / Hx, j = k % Hx;
        float s = 0.f;
        for (int d = 0; d < DHx; d++)
            s += outw[c * Dx + n * DHx + d] * g_E[br][2][j][n * DHx + d];
        g_P[br][k][c] = s;
    }
    float e0 = expf(alog[0]), e1 = expf(alog[1]);
    float alpha = (br == 0 ? e0 : e1) / (e0 + e1);
    for (int idx = tid; idx < Dx; idx += blockDim.x) {
        float s = outb[idx];
        for (int m = 0; m < Dx; m++) s += outw[idx * Dx + m] * vb[m];
        g_Pc[br][idx] = s;
        g_gw[br][idx] = ln2g[idx] * opw[idx] * alpha;
    }
    __syncthreads();
    __threadfence();
    if (tid == 0) {
        float sgw = 0.f, cst = 0.f;
        for (int c = 0; c < Dx; c++) { sgw += g_gw[br][c]; cst += ln2b[c] * opw[c]; }
        g_sc[br][0] = sgw;
        g_sc[br][1] = alpha * (cst + opb[0]);
    }
}

// ---------------------------------------------------------------------------
// Fused main kernel: 4 batch elems (96 rows) per 256-thread block, both branches
// ---------------------------------------------------------------------------
#define TSTR  133   // tsm / fesm row stride
#define PSTR  132   // Psm row stride (float4-aligned)
#define WSTR  97    // attention-weight row stride
#define W1STR 68    // W1^T [c][f] row stride (float4-aligned)
#define W2STR 132   // W2  [f][c] row stride (float4-aligned)
#define HSTR  69    // h row stride
#define SMEM_FLOATS 40376

__global__ __launch_bounds__(256)
void fused_main(const float* __restrict__ z, const float* __restrict__ fe,
                const float* __restrict__ ln1g, const float* __restrict__ ln1b,
                const float* __restrict__ w1, const float* __restrict__ b1,
                const float* __restrict__ w2, const float* __restrict__ b2,
                float* __restrict__ out) {
    extern __shared__ float sm[];
    float* zsm   = sm;            // 96
    float* outsm = sm + 96;       // 96
    float* c1g   = sm + 192;      // 128
    float* c1b   = sm + 320;      // 128
    float* cb2   = sm + 448;      // 128
    float* fesm  = sm + 576;      // 24*133 = 3192
    float* tsm   = sm + 3768;     // 96*133 = 12768
    float* X     = sm + 16536;    // union region: 23840 floats
    float* Psm = X;               // 96*132
    float* Wsm = X + 12672;       // 96*97
    float* W1T = X;               // 128*68
    float* W2s = X + 8704;        // 64*132
    float* hs  = X + 17152;       // 96*69
    float* b1c = X + 23776;       // 64

    int tid = threadIdx.x;
    int tx = tid & 15, ty = tid >> 4;
    int blk = blockIdx.x;
    int r0 = ty * 6, c0 = tx * 8;

    if (tid < 96) { zsm[tid] = z[blk * 96 + tid]; outsm[tid] = 0.f; }
    if (tid < 128) { c1g[tid] = ln1g[tid]; c1b[tid] = ln1b[tid]; cb2[tid] = b2[tid]; }
    for (int idx = tid; idx < Hx * Dx; idx += 256)
        fesm[(idx >> 7) * TSTR + (idx & 127)] = fe[idx];
    __syncthreads();

    for (int br = 0; br < 2; br++) {
        // ---- stage P ----
        const float* gP = &g_P[br][0][0];
        for (int idx = tid; idx < 96 * 128; idx += 256)
            Psm[(idx >> 7) * PSTR + (idx & 127)] = gP[idx];
        // ---- scores + softmax + weight fold (384 rows of 24) ----
        for (int rs = tid; rs < 384; rs += 256) {
            int bb = rs / 96, rem = rs % 96, n = rem / 24, i = rem % 24;
            float zi = zsm[bb * 24 + i];
            const float* Gp  = &g_G[br][n][i][0];
            const float* Mp  = &g_Mk[br][n][i][0];
            const float* gkp = &g_gk[br][n][0];
            float gq = g_gq[br][n][i];
            float s[24]; float mx = -1e30f;
            #pragma unroll
            for (int j = 0; j < 24; j++) {
                float zj = zsm[bb * 24 + j];
                float v = zi * zj * Gp[j] + zi * gq + zj * gkp[j] + Mp[j];
                s[j] = v; mx = fmaxf(mx, v);
            }
            float sum = 0.f;
            #pragma unroll
            for (int j = 0; j < 24; j++) {
                s[j] = __expf(fmaxf(s[j] - mx, -80.f));
                sum += s[j];
            }
            float inv = 1.f / sum;
            float* wrow = &Wsm[(bb * 24 + i) * WSTR + n * 24];
            #pragma unroll
            for (int j = 0; j < 24; j++) wrow[j] = s[j] * inv * zsm[bb * 24 + j];
        }
        __syncthreads();

        // ---- attention GEMM: o[96][128] = W[96][96] @ P[96][128] ----
        float acc[6][8];
        #pragma unroll
        for (int u = 0; u < 6; u++)
            #pragma unroll
            for (int v = 0; v < 8; v++) acc[u][v] = 0.f;
        for (int k = 0; k < 96; k++) {
            float wv[6];
            #pragma unroll
            for (int u = 0; u < 6; u++) wv[u] = Wsm[(r0 + u) * WSTR + k];
            float4 p0 = *(const float4*)&Psm[k * PSTR + c0];
            float4 p1 = *(const float4*)&Psm[k * PSTR + c0 + 4];
            #pragma unroll
            for (int u = 0; u < 6; u++) {
                acc[u][0] += wv[u] * p0.x; acc[u][1] += wv[u] * p0.y;
                acc[u][2] += wv[u] * p0.z; acc[u][3] += wv[u] * p0.w;
                acc[u][4] += wv[u] * p1.x; acc[u][5] += wv[u] * p1.y;
                acc[u][6] += wv[u] * p1.z; acc[u][7] += wv[u] * p1.w;
            }
        }
        // ---- + Pc + tokens, LN1, write t ----
        float4 pc0 = *(const float4*)&g_Pc[br][c0];
        float4 pc1 = *(const float4*)&g_Pc[br][c0 + 4];
        float pcv[8] = {pc0.x, pc0.y, pc0.z, pc0.w, pc1.x, pc1.y, pc1.z, pc1.w};
        #pragma unroll
        for (int u = 0; u < 6; u++) {
            int rr = r0 + u;
            int ii = rr % 24;
            float zr = zsm[rr];
            float y[8], s1 = 0.f, s2 = 0.f;
            #pragma unroll
            for (int v = 0; v < 8; v++) {
                float t = acc[u][v] + pcv[v] + zr * fesm[ii * TSTR + c0 + v];
                y[v] = t; s1 += t; s2 += t * t;
            }
            #pragma unroll
            for (int m = 8; m > 0; m >>= 1) {
                s1 += __shfl_xor_sync(0xffffffffu, s1, m);
                s2 += __shfl_xor_sync(0xffffffffu, s2, m);
            }
            float mean = s1 * (1.f / 128.f);
            float var = s2 * (1.f / 128.f) - mean * mean;
            float rstd = rsqrtf(var + 1e-5f);
            #pragma unroll
            for (int v = 0; v < 8; v++)
                tsm[rr * TSTR + c0 + v] = (y[v] - mean) * rstd * c1g[c0 + v] + c1b[c0 + v];
        }
        __syncthreads();   // t complete; Psm/Wsm dead -> reuse X for FFN staging

        // ---- FFN: 8 chunks of 64 ffn-dims ----
        float facc[6][8];
        #pragma unroll
        for (int u = 0; u < 6; u++)
            #pragma unroll
            for (int v = 0; v < 8; v++) facc[u][v] = 0.f;
        int fc0 = tx * 4;
        for (int ch = 0; ch < 8; ch++) {
            int f0 = ch * 64;
            for (int idx = tid; idx < 64 * 128; idx += 256) {
                int f = idx >> 7, c = idx & 127;
                W1T[c * W1STR + f] = w1[(f0 + f) * Dx + c];
            }
            for (int idx = tid; idx < 64 * 128; idx += 256) {
                int c = idx >> 6, f = idx & 63;
                W2s[f * W2STR + c] = w2[c * FFx + f0 + f];
            }
            if (tid < 64) b1c[tid] = b1[f0 + tid];
            __syncthreads();
            // GEMM1: h[96][64] = t[96][128] @ W1chunk^T, +b1, relu
            float hacc[6][4];
            #pragma unroll
            for (int u = 0; u < 6; u++)
                #pragma unroll
                for (int v = 0; v < 4; v++) hacc[u][v] = b1c[fc0 + v];
            for (int c = 0; c < 128; c++) {
                float tv[6];
                #pragma unroll
                for (int u = 0; u < 6; u++) tv[u] = tsm[(r0 + u) * TSTR + c];
                float4 wv = *(const float4*)&W1T[c * W1STR + fc0];
                #pragma unroll
                for (int u = 0; u < 6; u++) {
                    hacc[u][0] += tv[u] * wv.x; hacc[u][1] += tv[u] * wv.y;
                    hacc[u][2] += tv[u] * wv.z; hacc[u][3] += tv[u] * wv.w;
                }
            }
            #pragma unroll
            for (int u = 0; u < 6; u++)
                #pragma unroll
                for (int v = 0; v < 4; v++)
                    hs[(r0 + u) * HSTR + fc0 + v] = fmaxf(hacc[u][v], 0.f);
            __syncthreads();
            // GEMM2: facc[96][128] += h[96][64] @ W2chunk^T
            for (int f = 0; f < 64; f++) {
                float hv[6];
                #pragma unroll
                for (int u = 0; u < 6; u++) hv[u] = hs[(r0 + u) * HSTR + f];
                float4 wa = *(const float4*)&W2s[f * W2STR + c0];
                float4 wb = *(const float4*)&W2s[f * W2STR + c0 + 4];
                #pragma unroll
                for (int u = 0; u < 6; u++) {
                    facc[u][0] += hv[u] * wa.x; facc[u][1] += hv[u] * wa.y;
                    facc[u][2] += hv[u] * wa.z; facc[u][3] += hv[u] * wa.w;
                    facc[u][4] += hv[u] * wb.x; facc[u][5] += hv[u] * wb.y;
                    facc[u][6] += hv[u] * wb.z; facc[u][7] += hv[u] * wb.w;
                }
            }
            __syncthreads();   // before next chunk overwrites staging
        }
        // ---- epilogue: y = t + ffn + b2; fused LN2 + head via 3 reductions ----
        float4 gwa = *(const float4*)&g_gw[br][c0];
        float4 gwb = *(const float4*)&g_gw[br][c0 + 4];
        float gwv[8] = {gwa.x, gwa.y, gwa.z, gwa.w, gwb.x, gwb.y, gwb.z, gwb.w};
        float sgw = g_sc[br][0], cst = g_sc[br][1];
        #pragma unroll
        for (int u = 0; u < 6; u++) {
            int rr = r0 + u;
            float s1 = 0.f, s2 = 0.f, s3 = 0.f;
            #pragma unroll
            for (int v = 0; v < 8; v++) {
                float yv = tsm[rr * TSTR + c0 + v] + facc[u][v] + cb2[c0 + v];
                s1 += yv; s2 += yv * yv; s3 += yv * gwv[v];
            }
            #pragma unroll
            for (int m = 8; m > 0; m >>= 1) {
                s1 += __shfl_xor_sync(0xffffffffu, s1, m);
                s2 += __shfl_xor_sync(0xffffffffu, s2, m);
                s3 += __shfl_xor_sync(0xffffffffu, s3, m);
            }
            if (tx == 0) {
                float mean = s1 * (1.f / 128.f);
                float var = s2 * (1.f / 128.f) - mean * mean;
                float rstd = rsqrtf(var + 1e-5f);
                outsm[rr] += (s3 - mean * sgw) * rstd + cst;
            }
        }
        __syncthreads();   // before next branch reuses tsm / X
    }
    if (tid < 96) out[blk * 96 + tid] = outsm[tid];
}

// ---------------------------------------------------------------------------
// Launch
// ---------------------------------------------------------------------------
extern "C" void kernel_launch(void* const* d_in, const int* in_sizes, int n_in,
                              void* d_out, int out_size) {
    const float* z    = (const float*)d_in[0];
    const float* fe   = (const float*)d_in[1];
    const float* inwp = (const float*)d_in[2];
    const float* inbp = (const float*)d_in[3];
    const float* outwp= (const float*)d_in[4];
    const float* outbp= (const float*)d_in[5];
    const float* inwf = (const float*)d_in[6];
    const float* inbf = (const float*)d_in[7];
    const float* outwf= (const float*)d_in[8];
    const float* outbf= (const float*)d_in[9];
    const float* ln1g = (const float*)d_in[10];
    const float* ln1b = (const float*)d_in[11];
    const float* w1   = (const float*)d_in[12];
    const float* b1   = (const float*)d_in[13];
    const float* w2   = (const float*)d_in[14];
    const float* b2   = (const float*)d_in[15];
    const float* ln2g = (const float*)d_in[16];
    const float* ln2b = (const float*)d_in[17];
    const float* oppw = (const float*)d_in[18];
    const float* oppb = (const float*)d_in[19];
    const float* opfw = (const float*)d_in[20];
    const float* opfb = (const float*)d_in[21];
    const float* alog = (const float*)d_in[22];
    const float* bp   = (const float*)d_in[23];
    const float* bf   = (const float*)d_in[24];

    int B = in_sizes[0] / Hx;
    size_t smem = SMEM_FLOATS * sizeof(float);
    cudaFuncSetAttribute(fused_main, cudaFuncAttributeMaxDynamicSharedMemorySize, (int)smem);

    pre_qkv<<<6, 256>>>(fe, inwp, inwf);
    pre_misc<<<2, 256>>>(inbp, inbf, outwp, outbp, outwf, outbf,
                         ln2g, ln2b, oppw, oppb, opfw, opfb, alog, bp, bf);
    fused_main<<<B / 4, 256, smem>>>(z, fe, ln1g, ln1b, w1, b1, w2, b2, (float*)d_out);
}

// round 5
// speedup vs baseline: 2.5249x; 2.5249x over previous
#include <cuda_runtime.h>
#include <cuda_bf16.h>
#include <math.h>
#include <stdint.h>

#define Hx 24
#define Dx 128
#define NHx 4
#define DHx 32
#define RS32 0.17677669529663687f

// ------------------------- device globals -------------------------
__device__ float g_E[2][3][Hx][Dx];
__device__ float g_G[2][NHx][Hx][Hx];
__device__ float g_Mk[2][NHx][Hx][Hx];
__device__ float g_gq[2][NHx][Hx];
__device__ float g_gk[2][NHx][Hx];
__device__ float g_P[2][NHx*Hx][Dx];
__device__ float g_Pc[2][Dx];
__device__ float g_gw[2][Dx];
__device__ float g_sc[2][2];
__device__ unsigned int g_t[2][25165824u];          // packed bf16 hi | lo<<16
__device__ __nv_bfloat16 g_w1b[2][512][128];        // [hi/lo][f][c]
__device__ __nv_bfloat16 g_w2b[2][128][512];        // [hi/lo][c][f]

// ------------------------- helpers -------------------------
__device__ __forceinline__ uint32_t cvta_s(const void* p) {
    uint32_t a;
    asm("{ .reg .u64 t; cvta.to.shared.u64 t, %1; cvt.u32.u64 %0, t; }" : "=r"(a) : "l"(p));
    return a;
}
__device__ __forceinline__ void ldsm4(uint32_t addr, uint32_t& r0, uint32_t& r1,
                                      uint32_t& r2, uint32_t& r3) {
    asm volatile("ldmatrix.sync.aligned.m8n8.x4.shared.b16 {%0,%1,%2,%3}, [%4];"
                 : "=r"(r0), "=r"(r1), "=r"(r2), "=r"(r3) : "r"(addr));
}
__device__ __forceinline__ void mma_bf16(float d[4], uint32_t a0, uint32_t a1, uint32_t a2,
                                         uint32_t a3, uint32_t b0, uint32_t b1) {
    asm volatile("mma.sync.aligned.m16n8k16.row.col.f32.bf16.bf16.f32 "
                 "{%0,%1,%2,%3}, {%4,%5,%6,%7}, {%8,%9}, {%0,%1,%2,%3};"
                 : "+f"(d[0]), "+f"(d[1]), "+f"(d[2]), "+f"(d[3])
                 : "r"(a0), "r"(a1), "r"(a2), "r"(a3), "r"(b0), "r"(b1));
}
__device__ __forceinline__ uint32_t pk2(__nv_bfloat16 lo, __nv_bfloat16 hi) {
    return (uint32_t)__bfloat16_as_ushort(lo) | ((uint32_t)__bfloat16_as_ushort(hi) << 16);
}
__device__ __forceinline__ float bflo(uint32_t v) {
    return __bfloat162float(__ushort_as_bfloat16((unsigned short)(v & 0xFFFFu)));
}
__device__ __forceinline__ float bfhi(uint32_t v) {
    return __bfloat162float(__ushort_as_bfloat16((unsigned short)(v >> 16)));
}

// ------------------------- precompute 1 -------------------------
__global__ void pre_qkv(const float* __restrict__ fe, const float* __restrict__ inwp,
                        const float* __restrict__ inwf) {
    int br = blockIdx.x / 3, which = blockIdx.x % 3;
    const float* W = (br ? inwf : inwp) + which * Dx * Dx;
    __shared__ float fes[Hx * Dx];
    for (int idx = threadIdx.x; idx < Hx * Dx; idx += 256) fes[idx] = fe[idx];
    __syncthreads();
    for (int idx = blockIdx.y * 256 + threadIdx.x; idx < Hx * Dx; idx += 2048) {
        int i = idx >> 7, c = idx & 127;
        float s = 0.f;
        #pragma unroll 8
        for (int d = 0; d < Dx; d++) s += fes[i * Dx + d] * W[c * Dx + d];
        g_E[br][which][i][c] = s;
    }
}

// ------------------------- precompute 2 -------------------------
__global__ void pre_misc(const float* __restrict__ inbp, const float* __restrict__ inbf,
                         const float* __restrict__ outwp, const float* __restrict__ outbp,
                         const float* __restrict__ outwf, const float* __restrict__ outbf,
                         const float* __restrict__ ln2g, const float* __restrict__ ln2b,
                         const float* __restrict__ oppw, const float* __restrict__ oppb,
                         const float* __restrict__ opfw, const float* __restrict__ opfb,
                         const float* __restrict__ alog,
                         const float* __restrict__ biasp, const float* __restrict__ biasf) {
    int br = blockIdx.x, gy = blockIdx.y;
    const float* inb  = br ? inbf  : inbp;
    const float* outw = br ? outwf : outwp;
    const float* outb = br ? outbf : outbp;
    const float* opw  = br ? opfw  : oppw;
    const float* opb  = br ? opfb  : oppb;
    const float* bias = br ? biasf : biasp;
    const float* qb = inb, *kb = inb + Dx, *vb = inb + 2 * Dx;
    __shared__ float g0s[NHx];
    int tid = threadIdx.x;
    if (tid < NHx) {
        float s = 0.f;
        for (int d = 0; d < DHx; d++) s += qb[tid * DHx + d] * kb[tid * DHx + d];
        g0s[tid] = s * RS32;
    }
    __syncthreads();
    int base = gy * 256 + tid;
    for (int idx = base; idx < NHx * Hx; idx += 2048) {
        int n = idx / Hx, i = idx % Hx;
        float s1 = 0.f, s2 = 0.f;
        for (int d = 0; d < DHx; d++) {
            s1 += g_E[br][0][i][n * DHx + d] * kb[n * DHx + d];
            s2 += g_E[br][1][i][n * DHx + d] * qb[n * DHx + d];
        }
        g_gq[br][n][i] = s1 * RS32;
        g_gk[br][n][i] = s2 * RS32;
    }
    for (int idx = base; idx < NHx * Hx * Hx; idx += 2048) {
        int n = idx / (Hx * Hx), i = (idx / Hx) % Hx, j = idx % Hx;
        float s = 0.f;
        for (int d = 0; d < DHx; d++)
            s += g_E[br][0][i][n * DHx + d] * g_E[br][1][j][n * DHx + d];
        g_G[br][n][i][j] = s * RS32;
        bool valid = (br == 0) ? (j <= i) : (j >= i);
        g_Mk[br][n][i][j] = valid ? bias[j - i + Hx - 1] + g0s[n] : -1e30f;
    }
    for (int idx = base; idx < NHx * Hx * Dx; idx += 2048) {
        int k = idx >> 7, c = idx & 127;
        int n = k / Hx, j = k % Hx;
        float s = 0.f;
        for (int d = 0; d < DHx; d++)
            s += outw[c * Dx + n * DHx + d] * g_E[br][2][j][n * DHx + d];
        g_P[br][k][c] = s;
    }
    if (gy == 0) {
        float e0 = expf(alog[0]), e1 = expf(alog[1]);
        float alpha = (br == 0 ? e0 : e1) / (e0 + e1);
        for (int idx = tid; idx < Dx; idx += 256) {
            float s = outb[idx];
            for (int m = 0; m < Dx; m++) s += outw[idx * Dx + m] * vb[m];
            g_Pc[br][idx] = s;
            g_gw[br][idx] = ln2g[idx] * opw[idx] * alpha;
        }
        __syncthreads();
        __threadfence();
        if (tid == 0) {
            float sgw = 0.f, cst = 0.f;
            for (int c = 0; c < Dx; c++) { sgw += g_gw[br][c]; cst += ln2b[c] * opw[c]; }
            g_sc[br][0] = sgw;
            g_sc[br][1] = alpha * (cst + opb[0]);
        }
    }
}

// ------------------------- precompute 3: bf16 hi/lo weight images -------------------------
__global__ void pre_wimg(const float* __restrict__ w1, const float* __restrict__ w2) {
    int idx = blockIdx.x * 256 + threadIdx.x;
    if (idx >= 65536) return;
    {
        int f = idx >> 7, c = idx & 127;
        float v = w1[idx];
        __nv_bfloat16 h = __float2bfloat16(v);
        __nv_bfloat16 l = __float2bfloat16(v - __bfloat162float(h));
        g_w1b[0][f][c] = h;
        g_w1b[1][f][c] = l;
    }
    {
        int n = idx >> 9, ff = idx & 511;
        float v = w2[idx];
        __nv_bfloat16 h = __float2bfloat16(v);
        __nv_bfloat16 l = __float2bfloat16(v - __bfloat162float(h));
        g_w2b[0][n][ff] = h;
        g_w2b[1][n][ff] = l;
    }
}

// ------------------------- K2: attention + LN1 -> packed t -------------------------
#define TSTR 133
#define PSTR 132
#define WSTR 97
#define K2_FLOATS 25528

__global__ __launch_bounds__(256)
void attn_k(const float* __restrict__ z, const float* __restrict__ fe,
            const float* __restrict__ ln1g, const float* __restrict__ ln1b) {
    extern __shared__ float sm[];
    float* zsm  = sm;
    float* c1g  = sm + 96;
    float* c1b  = sm + 224;
    float* fesm = sm + 352;
    float* Psm  = sm + 3544;
    float* Wsm  = sm + 16216;
    int tid = threadIdx.x, tx = tid & 15, ty = tid >> 4;
    int blk = blockIdx.x, r0 = ty * 6, c0 = tx * 8;

    if (tid < 96) zsm[tid] = z[blk * 96 + tid];
    if (tid < 128) { c1g[tid] = ln1g[tid]; c1b[tid] = ln1b[tid]; }
    for (int idx = tid; idx < Hx * Dx; idx += 256)
        fesm[(idx >> 7) * TSTR + (idx & 127)] = fe[idx];
    __syncthreads();

    for (int br = 0; br < 2; br++) {
        const float* gP = &g_P[br][0][0];
        for (int idx = tid; idx < 96 * 128; idx += 256)
            Psm[(idx >> 7) * PSTR + (idx & 127)] = gP[idx];
        for (int rs = tid; rs < 384; rs += 256) {
            int bb = rs / 96, rem = rs % 96, n = rem / 24, i = rem % 24;
            float zi = zsm[bb * 24 + i];
            const float* Gp = &g_G[br][n][i][0];
            const float* Mp = &g_Mk[br][n][i][0];
            const float* gkp = &g_gk[br][n][0];
            float gq = g_gq[br][n][i];
            float s[24]; float mx = -1e30f;
            #pragma unroll
            for (int j = 0; j < 24; j++) {
                float zj = zsm[bb * 24 + j];
                float v = zi * zj * Gp[j] + zi * gq + zj * gkp[j] + Mp[j];
                s[j] = v; mx = fmaxf(mx, v);
            }
            float sum = 0.f;
            #pragma unroll
            for (int j = 0; j < 24; j++) { s[j] = __expf(fmaxf(s[j] - mx, -80.f)); sum += s[j]; }
            float inv = 1.f / sum;
            float* wrow = &Wsm[(bb * 24 + i) * WSTR + n * 24];
            #pragma unroll
            for (int j = 0; j < 24; j++) wrow[j] = s[j] * inv * zsm[bb * 24 + j];
        }
        __syncthreads();
        float acc[6][8];
        #pragma unroll
        for (int u = 0; u < 6; u++)
            #pragma unroll
            for (int v = 0; v < 8; v++) acc[u][v] = 0.f;
        for (int k = 0; k < 96; k++) {
            float wv[6];
            #pragma unroll
            for (int u = 0; u < 6; u++) wv[u] = Wsm[(r0 + u) * WSTR + k];
            float4 p0 = *(const float4*)&Psm[k * PSTR + c0];
            float4 p1 = *(const float4*)&Psm[k * PSTR + c0 + 4];
            #pragma unroll
            for (int u = 0; u < 6; u++) {
                acc[u][0] += wv[u] * p0.x; acc[u][1] += wv[u] * p0.y;
                acc[u][2] += wv[u] * p0.z; acc[u][3] += wv[u] * p0.w;
                acc[u][4] += wv[u] * p1.x; acc[u][5] += wv[u] * p1.y;
                acc[u][6] += wv[u] * p1.z; acc[u][7] += wv[u] * p1.w;
            }
        }
        float4 pc0 = *(const float4*)&g_Pc[br][c0];
        float4 pc1 = *(const float4*)&g_Pc[br][c0 + 4];
        float pcv[8] = {pc0.x, pc0.y, pc0.z, pc0.w, pc1.x, pc1.y, pc1.z, pc1.w};
        #pragma unroll
        for (int u = 0; u < 6; u++) {
            int rr = r0 + u, ii = rr % 24;
            float zr = zsm[rr];
            float y[8], s1 = 0.f, s2 = 0.f;
            #pragma unroll
            for (int v = 0; v < 8; v++) {
                float t = acc[u][v] + pcv[v] + zr * fesm[ii * TSTR + c0 + v];
                y[v] = t; s1 += t; s2 += t * t;
            }
            #pragma unroll
            for (int m = 8; m > 0; m >>= 1) {
                s1 += __shfl_xor_sync(0xffffffffu, s1, m);
                s2 += __shfl_xor_sync(0xffffffffu, s2, m);
            }
            float mean = s1 * (1.f / 128.f);
            float var = s2 * (1.f / 128.f) - mean * mean;
            float rstd = rsqrtf(var + 1e-5f);
            unsigned int pk[8];
            #pragma unroll
            for (int v = 0; v < 8; v++) {
                float t = (y[v] - mean) * rstd * c1g[c0 + v] + c1b[c0 + v];
                __nv_bfloat16 hb = __float2bfloat16(t);
                __nv_bfloat16 lb = __float2bfloat16(t - __bfloat162float(hb));
                pk[v] = (unsigned int)__bfloat16_as_ushort(hb) |
                        ((unsigned int)__bfloat16_as_ushort(lb) << 16);
            }
            unsigned int* dst = &g_t[br][(size_t)(blk * 96 + rr) * 128 + c0];
            ((uint4*)dst)[0] = make_uint4(pk[0], pk[1], pk[2], pk[3]);
            ((uint4*)dst)[1] = make_uint4(pk[4], pk[5], pk[6], pk[7]);
        }
        __syncthreads();
    }
}

// ------------------------- K3: FFN via mma.sync (bf16 x3) + LN2/head -------------------------
#define TAH_OFF 0
#define TAL_OFF 69632
#define W1H_OFF 139264
#define W1L_OFF 156672
#define W2H_OFF 174080
#define W2L_OFF 192512
#define B1C_OFF 210944
#define GWS_OFF 211200
#define B2S_OFF 212224
#define SM3 212736

__global__ __launch_bounds__(256, 1)
void ffn_mma(const float* __restrict__ b1g, const float* __restrict__ b2g,
             float* __restrict__ out) {
    extern __shared__ char smc[];
    uint32_t sb = cvta_s(smc);
    int tid = threadIdx.x, wid = tid >> 5, lane = tid & 31;
    int tile = blockIdx.x;
    int g = lane >> 3;
    int m0 = wid * 16;

    float* b1c = (float*)(smc + B1C_OFF);
    float* gws = (float*)(smc + GWS_OFF);
    float* b2s = (float*)(smc + B2S_OFF);
    if (tid < 128) { gws[tid] = g_gw[0][tid]; gws[128 + tid] = g_gw[1][tid]; }
    else { b2s[tid - 128] = b2g[tid - 128]; }

    // stage t tile (both branches): unpack hi/lo into padded bf16 rows
    for (int br = 0; br < 2; br++) {
        const uint2* src = (const uint2*)&g_t[br][(size_t)tile * 16384];
        for (int idx = tid; idx < 8192; idx += 256) {
            uint2 v = src[idx];
            int r = idx >> 6, pr = idx & 63;
            uint32_t hi = (v.x & 0xFFFFu) | (v.y << 16);
            uint32_t lo = (v.x >> 16) | (v.y & 0xFFFF0000u);
            uint32_t boff = (uint32_t)(br * 128 + r) * 272u + (uint32_t)pr * 4u;
            *(uint32_t*)(smc + TAH_OFF + boff) = hi;
            *(uint32_t*)(smc + TAL_OFF + boff) = lo;
        }
    }
    __syncthreads();

    // per-lane ldmatrix address components
    uint32_t aRowOff = (uint32_t)((lane & 7) + ((g & 1) << 3));
    uint32_t aKOff   = (uint32_t)((g >> 1) << 4);
    uint32_t bPart272 = (uint32_t)(((lane & 7) + ((g >> 1) << 3)) * 272 + ((g & 1) << 4));
    uint32_t bPart144 = (uint32_t)(((lane & 7) + ((g >> 1) << 3)) * 144 + ((g & 1) << 4));

    float resA = 0.f, resB = 0.f;

    for (int br = 0; br < 2; br++) {
        float accF[16][4];
        #pragma unroll
        for (int q = 0; q < 16; q++)
            #pragma unroll
            for (int v = 0; v < 4; v++) accF[q][v] = 0.f;

        uint32_t aBaseRow = (uint32_t)(br * 128 + m0) + aRowOff;

        for (int ch = 0; ch < 8; ch++) {
            // ---- stage W1/W2 chunk ----
            {
                const uint4* s0 = (const uint4*)&g_w1b[0][ch * 64][0];
                const uint4* s1 = (const uint4*)&g_w1b[1][ch * 64][0];
                for (int i = tid; i < 1024; i += 256) {
                    int row = i >> 4, col = i & 15;
                    *(uint4*)(smc + W1H_OFF + row * 272 + col * 16) = s0[i];
                    *(uint4*)(smc + W1L_OFF + row * 272 + col * 16) = s1[i];
                }
                const uint4* t0 = (const uint4*)&g_w2b[0][0][0];
                const uint4* t1 = (const uint4*)&g_w2b[1][0][0];
                for (int i = tid; i < 1024; i += 256) {
                    int row = i >> 3, col = i & 7;
                    *(uint4*)(smc + W2H_OFF + row * 144 + col * 16) = t0[row * 64 + ch * 8 + col];
                    *(uint4*)(smc + W2L_OFF + row * 144 + col * 16) = t1[row * 64 + ch * 8 + col];
                }
                if (tid < 64) b1c[tid] = b1g[ch * 64 + tid];
            }
            __syncthreads();

            // ---- GEMM1: h[16][64] = t[16][128] @ W1ch^T  (3 bf16 passes) ----
            float acc1[8][4];
            #pragma unroll
            for (int q = 0; q < 8; q++)
                #pragma unroll
                for (int v = 0; v < 4; v++) acc1[q][v] = 0.f;
            #pragma unroll
            for (int p = 0; p < 3; p++) {
                uint32_t aBase = sb + (p == 2 ? TAL_OFF : TAH_OFF) + aBaseRow * 272u + aKOff;
                uint32_t bBase = sb + (p == 1 ? W1L_OFF : W1H_OFF) + bPart272;
                #pragma unroll
                for (int k = 0; k < 8; k++) {
                    uint32_t a0, a1, a2, a3;
                    ldsm4(aBase + (uint32_t)k * 32u, a0, a1, a2, a3);
                    #pragma unroll
                    for (int q = 0; q < 4; q++) {
                        uint32_t r0, r1, r2, r3;
                        ldsm4(bBase + (uint32_t)(q * 16 * 272) + (uint32_t)k * 32u, r0, r1, r2, r3);
                        mma_bf16(acc1[2 * q],     a0, a1, a2, a3, r0, r1);
                        mma_bf16(acc1[2 * q + 1], a0, a1, a2, a3, r2, r3);
                    }
                }
            }
            // ---- bias + relu + split into GEMM2 A-fragments (registers only) ----
            uint32_t ah[8][2], al[8][2];
            #pragma unroll
            for (int t = 0; t < 8; t++) {
                int cc = t * 8 + ((lane & 3) << 1);
                float bb0 = b1c[cc], bb1 = b1c[cc + 1];
                float h0 = fmaxf(acc1[t][0] + bb0, 0.f);
                float h1 = fmaxf(acc1[t][1] + bb1, 0.f);
                float h2 = fmaxf(acc1[t][2] + bb0, 0.f);
                float h3 = fmaxf(acc1[t][3] + bb1, 0.f);
                __nv_bfloat16 q0 = __float2bfloat16(h0), q1 = __float2bfloat16(h1);
                __nv_bfloat16 q2 = __float2bfloat16(h2), q3 = __float2bfloat16(h3);
                ah[t][0] = pk2(q0, q1);
                ah[t][1] = pk2(q2, q3);
                al[t][0] = pk2(__float2bfloat16(h0 - __bfloat162float(q0)),
                               __float2bfloat16(h1 - __bfloat162float(q1)));
                al[t][1] = pk2(__float2bfloat16(h2 - __bfloat162float(q2)),
                               __float2bfloat16(h3 - __bfloat162float(q3)));
            }
            // ---- GEMM2: accF += h[16][64] @ W2ch^T  (3 passes) ----
            #pragma unroll
            for (int p = 0; p < 3; p++) {
                uint32_t bBase = sb + (p == 1 ? W2L_OFF : W2H_OFF) + bPart144;
                #pragma unroll
                for (int ks = 0; ks < 4; ks++) {
                    uint32_t a0 = (p == 2) ? al[2 * ks][0]     : ah[2 * ks][0];
                    uint32_t a1 = (p == 2) ? al[2 * ks][1]     : ah[2 * ks][1];
                    uint32_t a2 = (p == 2) ? al[2 * ks + 1][0] : ah[2 * ks + 1][0];
                    uint32_t a3 = (p == 2) ? al[2 * ks + 1][1] : ah[2 * ks + 1][1];
                    #pragma unroll
                    for (int q = 0; q < 8; q++) {
                        uint32_t r0, r1, r2, r3;
                        ldsm4(bBase + (uint32_t)(q * 16 * 144) + (uint32_t)ks * 32u, r0, r1, r2, r3);
                        mma_bf16(accF[2 * q],     a0, a1, a2, a3, r0, r1);
                        mma_bf16(accF[2 * q + 1], a0, a1, a2, a3, r2, r3);
                    }
                }
            }
            __syncthreads();
        }

        // ---- epilogue: residual + fused LN2 + head ----
        float sA0 = 0.f, sA1 = 0.f, sA2 = 0.f, sB0 = 0.f, sB1 = 0.f, sB2 = 0.f;
        int ra = br * 128 + m0 + (lane >> 2);
        #pragma unroll
        for (int t = 0; t < 16; t++) {
            int c = t * 8 + ((lane & 3) << 1);
            uint32_t hia = *(const uint32_t*)(smc + TAH_OFF + ra * 272 + c * 2);
            uint32_t loa = *(const uint32_t*)(smc + TAL_OFF + ra * 272 + c * 2);
            uint32_t hib = *(const uint32_t*)(smc + TAH_OFF + (ra + 8) * 272 + c * 2);
            uint32_t lob = *(const uint32_t*)(smc + TAL_OFF + (ra + 8) * 272 + c * 2);
            float t0a = bflo(hia) + bflo(loa), t1a = bfhi(hia) + bfhi(loa);
            float t0b = bflo(hib) + bflo(lob), t1b = bfhi(hib) + bfhi(lob);
            float bz0 = b2s[c], bz1 = b2s[c + 1];
            float g0 = gws[br * 128 + c], g1 = gws[br * 128 + c + 1];
            float y0 = accF[t][0] + t0a + bz0;
            float y1 = accF[t][1] + t1a + bz1;
            float y2 = accF[t][2] + t0b + bz0;
            float y3 = accF[t][3] + t1b + bz1;
            sA0 += y0 + y1; sA1 += y0 * y0 + y1 * y1; sA2 += y0 * g0 + y1 * g1;
            sB0 += y2 + y3; sB1 += y2 * y2 + y3 * y3; sB2 += y2 * g0 + y3 * g1;
        }
        #pragma unroll
        for (int m = 1; m < 4; m <<= 1) {
            sA0 += __shfl_xor_sync(0xffffffffu, sA0, m);
            sA1 += __shfl_xor_sync(0xffffffffu, sA1, m);
            sA2 += __shfl_xor_sync(0xffffffffu, sA2, m);
            sB0 += __shfl_xor_sync(0xffffffffu, sB0, m);
            sB1 += __shfl_xor_sync(0xffffffffu, sB1, m);
            sB2 += __shfl_xor_sync(0xffffffffu, sB2, m);
        }
        float sgw = g_sc[br][0], cst = g_sc[br][1];
        {
            float mean = sA0 * (1.f / 128.f);
            float var = sA1 * (1.f / 128.f) - mean * mean;
            resA += (sA2 - mean * sgw) * rsqrtf(var + 1e-5f) + cst;
            float meanb = sB0 * (1.f / 128.f);
            float varb = sB1 * (1.f / 128.f) - meanb * meanb;
            resB += (sB2 - meanb * sgw) * rsqrtf(varb + 1e-5f) + cst;
        }
    }
    if ((lane & 3) == 0) {
        out[(size_t)tile * 128 + m0 + (lane >> 2)] = resA;
        out[(size_t)tile * 128 + m0 + 8 + (lane >> 2)] = resB;
    }
}

// ------------------------- launch -------------------------
extern "C" void kernel_launch(void* const* d_in, const int* in_sizes, int n_in,
                              void* d_out, int out_size) {
    const float* z    = (const float*)d_in[0];
    const float* fe   = (const float*)d_in[1];
    const float* inwp = (const float*)d_in[2];
    const float* inbp = (const float*)d_in[3];
    const float* outwp= (const float*)d_in[4];
    const float* outbp= (const float*)d_in[5];
    const float* inwf = (const float*)d_in[6];
    const float* inbf = (const float*)d_in[7];
    const float* outwf= (const float*)d_in[8];
    const float* outbf= (const float*)d_in[9];
    const float* ln1g = (const float*)d_in[10];
    const float* ln1b = (const float*)d_in[11];
    const float* w1   = (const float*)d_in[12];
    const float* b1   = (const float*)d_in[13];
    const float* w2   = (const float*)d_in[14];
    const float* b2   = (const float*)d_in[15];
    const float* ln2g = (const float*)d_in[16];
    const float* ln2b = (const float*)d_in[17];
    const float* oppw = (const float*)d_in[18];
    const float* oppb = (const float*)d_in[19];
    const float* opfw = (const float*)d_in[20];
    const float* opfb = (const float*)d_in[21];
    const float* alog = (const float*)d_in[22];
    const float* bp   = (const float*)d_in[23];
    const float* bf   = (const float*)d_in[24];

    int B = in_sizes[0] / Hx;
    int tiles = (B * Hx) / 128;
    cudaFuncSetAttribute(attn_k, cudaFuncAttributeMaxDynamicSharedMemorySize, K2_FLOATS * 4);
    cudaFuncSetAttribute(ffn_mma, cudaFuncAttributeMaxDynamicSharedMemorySize, SM3);

    pre_qkv<<<dim3(6, 8), 256>>>(fe, inwp, inwf);
    pre_misc<<<dim3(2, 8), 256>>>(inbp, inbf, outwp, outbp, outwf, outbf,
                                  ln2g, ln2b, oppw, oppb, opfw, opfb, alog, bp, bf);
    pre_wimg<<<256, 256>>>(w1, w2);
    attn_k<<<B / 4, 256, K2_FLOATS * 4>>>(z, fe, ln1g, ln1b);
    ffn_mma<<<tiles, 256, SM3>>>(b1, b2, (float*)d_out);
}

// round 6
// speedup vs baseline: 3.6996x; 1.4652x over previous
#include <cuda_runtime.h>
#include <cuda_fp16.h>
#include <math.h>
#include <stdint.h>

#define Hx 24
#define Dx 128
#define NHx 4
#define DHx 32
#define RS32 0.17677669529663687f

// ------------------------- device globals -------------------------
__device__ float g_E[2][3][Hx][Dx];
__device__ float g_G[2][NHx][Hx][Hx];
__device__ float g_Mk[2][NHx][Hx][Hx];
__device__ float g_gq[2][NHx][Hx];
__device__ float g_gk[2][NHx][Hx];
__device__ float g_P[2][NHx*Hx][Dx];
__device__ float g_Pc[2][Dx];
__device__ float g_gw[2][Dx];
__device__ float g_sc[2][2];
__device__ unsigned int g_t[2][25165824u];   // packed fp16 hi | lo<<16
__device__ __half g_w1h[512][128];           // fp16 weights
__device__ __half g_w2h[128][512];

// ------------------------- helpers -------------------------
__device__ __forceinline__ uint32_t cvta_s(const void* p) {
    uint32_t a;
    asm("{ .reg .u64 t; cvta.to.shared.u64 t, %1; cvt.u32.u64 %0, t; }" : "=r"(a) : "l"(p));
    return a;
}
__device__ __forceinline__ void ldsm4(uint32_t addr, uint32_t& r0, uint32_t& r1,
                                      uint32_t& r2, uint32_t& r3) {
    asm volatile("ldmatrix.sync.aligned.m8n8.x4.shared.b16 {%0,%1,%2,%3}, [%4];"
                 : "=r"(r0), "=r"(r1), "=r"(r2), "=r"(r3) : "r"(addr));
}
__device__ __forceinline__ void mma_f16(float d[4], uint32_t a0, uint32_t a1, uint32_t a2,
                                        uint32_t a3, uint32_t b0, uint32_t b1) {
    asm volatile("mma.sync.aligned.m16n8k16.row.col.f32.f16.f16.f32 "
                 "{%0,%1,%2,%3}, {%4,%5,%6,%7}, {%8,%9}, {%0,%1,%2,%3};"
                 : "+f"(d[0]), "+f"(d[1]), "+f"(d[2]), "+f"(d[3])
                 : "r"(a0), "r"(a1), "r"(a2), "r"(a3), "r"(b0), "r"(b1));
}
__device__ __forceinline__ uint32_t pk2h(__half e0, __half e1) {
    return (uint32_t)__half_as_ushort(e0) | ((uint32_t)__half_as_ushort(e1) << 16);
}
__device__ __forceinline__ float hLO(uint32_t v) {
    return __half2float(__ushort_as_half((unsigned short)(v & 0xFFFFu)));
}
__device__ __forceinline__ float hHI(uint32_t v) {
    return __half2float(__ushort_as_half((unsigned short)(v >> 16)));
}
#define CPA16(d, s) asm volatile("cp.async.cg.shared.global [%0], [%1], 16;" :: "r"(d), "l"(s))
#define CPA_COMMIT() asm volatile("cp.async.commit_group;" ::: "memory")

// ------------------------- precompute 1 -------------------------
__global__ void pre_qkv(const float* __restrict__ fe, const float* __restrict__ inwp,
                        const float* __restrict__ inwf) {
    int br = blockIdx.x / 3, which = blockIdx.x % 3;
    const float* W = (br ? inwf : inwp) + which * Dx * Dx;
    __shared__ float fes[Hx * Dx];
    for (int idx = threadIdx.x; idx < Hx * Dx; idx += 256) fes[idx] = fe[idx];
    __syncthreads();
    for (int idx = blockIdx.y * 256 + threadIdx.x; idx < Hx * Dx; idx += 2048) {
        int i = idx >> 7, c = idx & 127;
        float s = 0.f;
        #pragma unroll 8
        for (int d = 0; d < Dx; d++) s += fes[i * Dx + d] * W[c * Dx + d];
        g_E[br][which][i][c] = s;
    }
}

// ------------------------- precompute 2 -------------------------
__global__ void pre_misc(const float* __restrict__ inbp, const float* __restrict__ inbf,
                         const float* __restrict__ outwp, const float* __restrict__ outbp,
                         const float* __restrict__ outwf, const float* __restrict__ outbf,
                         const float* __restrict__ ln2g, const float* __restrict__ ln2b,
                         const float* __restrict__ oppw, const float* __restrict__ oppb,
                         const float* __restrict__ opfw, const float* __restrict__ opfb,
                         const float* __restrict__ alog,
                         const float* __restrict__ biasp, const float* __restrict__ biasf) {
    int br = blockIdx.x, gy = blockIdx.y;
    const float* inb  = br ? inbf  : inbp;
    const float* outw = br ? outwf : outwp;
    const float* outb = br ? outbf : outbp;
    const float* opw  = br ? opfw  : oppw;
    const float* opb  = br ? opfb  : oppb;
    const float* bias = br ? biasf : biasp;
    const float* qb = inb, *kb = inb + Dx, *vb = inb + 2 * Dx;
    __shared__ float g0s[NHx];
    int tid = threadIdx.x;
    if (tid < NHx) {
        float s = 0.f;
        for (int d = 0; d < DHx; d++) s += qb[tid * DHx + d] * kb[tid * DHx + d];
        g0s[tid] = s * RS32;
    }
    __syncthreads();
    int base = gy * 256 + tid;
    for (int idx = base; idx < NHx * Hx; idx += 2048) {
        int n = idx / Hx, i = idx % Hx;
        float s1 = 0.f, s2 = 0.f;
        for (int d = 0; d < DHx; d++) {
            s1 += g_E[br][0][i][n * DHx + d] * kb[n * DHx + d];
            s2 += g_E[br][1][i][n * DHx + d] * qb[n * DHx + d];
        }
        g_gq[br][n][i] = s1 * RS32;
        g_gk[br][n][i] = s2 * RS32;
    }
    for (int idx = base; idx < NHx * Hx * Hx; idx += 2048) {
        int n = idx / (Hx * Hx), i = (idx / Hx) % Hx, j = idx % Hx;
        float s = 0.f;
        for (int d = 0; d < DHx; d++)
            s += g_E[br][0][i][n * DHx + d] * g_E[br][1][j][n * DHx + d];
        g_G[br][n][i][j] = s * RS32;
        bool valid = (br == 0) ? (j <= i) : (j >= i);
        g_Mk[br][n][i][j] = valid ? bias[j - i + Hx - 1] + g0s[n] : -1e30f;
    }
    for (int idx = base; idx < NHx * Hx * Dx; idx += 2048) {
        int k = idx >> 7, c = idx & 127;
        int n = k / Hx, j = k % Hx;
        float s = 0.f;
        for (int d = 0; d < DHx; d++)
            s += outw[c * Dx + n * DHx + d] * g_E[br][2][j][n * DHx + d];
        g_P[br][k][c] = s;
    }
    if (gy == 0) {
        float e0 = expf(alog[0]), e1 = expf(alog[1]);
        float alpha = (br == 0 ? e0 : e1) / (e0 + e1);
        for (int idx = tid; idx < Dx; idx += 256) {
            float s = outb[idx];
            for (int m = 0; m < Dx; m++) s += outw[idx * Dx + m] * vb[m];
            g_Pc[br][idx] = s;
            g_gw[br][idx] = ln2g[idx] * opw[idx] * alpha;
        }
        __syncthreads();
        __threadfence();
        if (tid == 0) {
            float sgw = 0.f, cst = 0.f;
            for (int c = 0; c < Dx; c++) { sgw += g_gw[br][c]; cst += ln2b[c] * opw[c]; }
            g_sc[br][0] = sgw;
            g_sc[br][1] = alpha * (cst + opb[0]);
        }
    }
}

// ------------------------- precompute 3: fp16 weight images -------------------------
__global__ void pre_wimg(const float* __restrict__ w1, const float* __restrict__ w2) {
    int idx = blockIdx.x * 256 + threadIdx.x;
    if (idx >= 65536) return;
    {
        int f = idx >> 7, c = idx & 127;
        g_w1h[f][c] = __float2half_rn(w1[idx]);
    }
    {
        int n = idx >> 9, ff = idx & 511;
        g_w2h[n][ff] = __float2half_rn(w2[idx]);
    }
}

// ------------------------- K2: attention + LN1 -> packed fp16 t -------------------------
#define TSTR 133
#define PSTR 132
#define WSTR 97
#define K2_FLOATS 25528

__global__ __launch_bounds__(256)
void attn_k(const float* __restrict__ z, const float* __restrict__ fe,
            const float* __restrict__ ln1g, const float* __restrict__ ln1b) {
    extern __shared__ float sm[];
    float* zsm  = sm;
    float* c1g  = sm + 96;
    float* c1b  = sm + 224;
    float* fesm = sm + 352;
    float* Psm  = sm + 3544;
    float* Wsm  = sm + 16216;
    int tid = threadIdx.x, tx = tid & 15, ty = tid >> 4;
    int blk = blockIdx.x, r0 = ty * 6, c0 = tx * 8;

    if (tid < 96) zsm[tid] = z[blk * 96 + tid];
    if (tid < 128) { c1g[tid] = ln1g[tid]; c1b[tid] = ln1b[tid]; }
    for (int idx = tid; idx < Hx * Dx; idx += 256)
        fesm[(idx >> 7) * TSTR + (idx & 127)] = fe[idx];
    __syncthreads();

    for (int br = 0; br < 2; br++) {
        const float* gP = &g_P[br][0][0];
        for (int idx = tid; idx < 96 * 128; idx += 256)
            Psm[(idx >> 7) * PSTR + (idx & 127)] = gP[idx];
        for (int rs = tid; rs < 384; rs += 256) {
            int bb = rs / 96, rem = rs % 96, n = rem / 24, i = rem % 24;
            float zi = zsm[bb * 24 + i];
            const float* Gp = &g_G[br][n][i][0];
            const float* Mp = &g_Mk[br][n][i][0];
            const float* gkp = &g_gk[br][n][0];
            float gq = g_gq[br][n][i];
            float s[24]; float mx = -1e30f;
            #pragma unroll
            for (int j = 0; j < 24; j++) {
                float zj = zsm[bb * 24 + j];
                float v = zi * zj * Gp[j] + zi * gq + zj * gkp[j] + Mp[j];
                s[j] = v; mx = fmaxf(mx, v);
            }
            float sum = 0.f;
            #pragma unroll
            for (int j = 0; j < 24; j++) { s[j] = __expf(fmaxf(s[j] - mx, -80.f)); sum += s[j]; }
            float inv = 1.f / sum;
            float* wrow = &Wsm[(bb * 24 + i) * WSTR + n * 24];
            #pragma unroll
            for (int j = 0; j < 24; j++) wrow[j] = s[j] * inv * zsm[bb * 24 + j];
        }
        __syncthreads();
        float acc[6][8];
        #pragma unroll
        for (int u = 0; u < 6; u++)
            #pragma unroll
            for (int v = 0; v < 8; v++) acc[u][v] = 0.f;
        for (int k = 0; k < 96; k++) {
            float wv[6];
            #pragma unroll
            for (int u = 0; u < 6; u++) wv[u] = Wsm[(r0 + u) * WSTR + k];
            float4 p0 = *(const float4*)&Psm[k * PSTR + c0];
            float4 p1 = *(const float4*)&Psm[k * PSTR + c0 + 4];
            #pragma unroll
            for (int u = 0; u < 6; u++) {
                acc[u][0] += wv[u] * p0.x; acc[u][1] += wv[u] * p0.y;
                acc[u][2] += wv[u] * p0.z; acc[u][3] += wv[u] * p0.w;
                acc[u][4] += wv[u] * p1.x; acc[u][5] += wv[u] * p1.y;
                acc[u][6] += wv[u] * p1.z; acc[u][7] += wv[u] * p1.w;
            }
        }
        float4 pc0 = *(const float4*)&g_Pc[br][c0];
        float4 pc1 = *(const float4*)&g_Pc[br][c0 + 4];
        float pcv[8] = {pc0.x, pc0.y, pc0.z, pc0.w, pc1.x, pc1.y, pc1.z, pc1.w};
        #pragma unroll
        for (int u = 0; u < 6; u++) {
            int rr = r0 + u, ii = rr % 24;
            float zr = zsm[rr];
            float y[8], s1 = 0.f, s2 = 0.f;
            #pragma unroll
            for (int v = 0; v < 8; v++) {
                float t = acc[u][v] + pcv[v] + zr * fesm[ii * TSTR + c0 + v];
                y[v] = t; s1 += t; s2 += t * t;
            }
            #pragma unroll
            for (int m = 8; m > 0; m >>= 1) {
                s1 += __shfl_xor_sync(0xffffffffu, s1, m);
                s2 += __shfl_xor_sync(0xffffffffu, s2, m);
            }
            float mean = s1 * (1.f / 128.f);
            float var = s2 * (1.f / 128.f) - mean * mean;
            float rstd = rsqrtf(var + 1e-5f);
            unsigned int pk[8];
            #pragma unroll
            for (int v = 0; v < 8; v++) {
                float t = (y[v] - mean) * rstd * c1g[c0 + v] + c1b[c0 + v];
                __half hb = __float2half_rn(t);
                __half lb = __float2half_rn(t - __half2float(hb));
                pk[v] = (unsigned int)__half_as_ushort(hb) |
                        ((unsigned int)__half_as_ushort(lb) << 16);
            }
            unsigned int* dst = &g_t[br][(size_t)(blk * 96 + rr) * 128 + c0];
            ((uint4*)dst)[0] = make_uint4(pk[0], pk[1], pk[2], pk[3]);
            ((uint4*)dst)[1] = make_uint4(pk[4], pk[5], pk[6], pk[7]);
        }
        __syncthreads();
    }
}

// ------------------------- K3: FFN fp16 x2 via mma.sync + cp.async -------------------------
#define TAH_OFF 0
#define TAL_OFF 69632
#define W1B_OFF 139264   /* 2 bufs x 64 rows x 272 B = 2 x 17408 */
#define W2B_OFF 174080   /* 2 bufs x 128 rows x 144 B = 2 x 18432 */
#define B1S_OFF 210944   /* 512 floats */
#define GWS_OFF 212992   /* 256 floats */
#define B2S_OFF 214016   /* 128 floats */
#define SM3 214528

__global__ __launch_bounds__(256, 1)
void ffn_mma(const float* __restrict__ b1g, const float* __restrict__ b2g,
             float* __restrict__ out) {
    extern __shared__ char smc[];
    uint32_t sb = cvta_s(smc);
    int tid = threadIdx.x, wid = tid >> 5, lane = tid & 31;
    int tile = blockIdx.x;
    int g = lane >> 3;
    int m0 = wid * 16;

    float* b1s = (float*)(smc + B1S_OFF);
    float* gws = (float*)(smc + GWS_OFF);
    float* b2s = (float*)(smc + B2S_OFF);
    if (tid < 128) { gws[tid] = g_gw[0][tid]; gws[128 + tid] = g_gw[1][tid]; }
    else { b2s[tid - 128] = b2g[tid - 128]; }
    for (int idx = tid; idx < 512; idx += 256) b1s[idx] = b1g[idx];

    // stage t tile (both branches): unpack fp16 hi/lo into padded rows
    for (int br = 0; br < 2; br++) {
        const uint2* src = (const uint2*)&g_t[br][(size_t)tile * 16384];
        for (int idx = tid; idx < 8192; idx += 256) {
            uint2 v = src[idx];
            int r = idx >> 6, pr = idx & 63;
            uint32_t hi = (v.x & 0xFFFFu) | (v.y << 16);
            uint32_t lo = (v.x >> 16) | (v.y & 0xFFFF0000u);
            uint32_t boff = (uint32_t)(br * 128 + r) * 272u + (uint32_t)pr * 4u;
            *(uint32_t*)(smc + TAH_OFF + boff) = hi;
            *(uint32_t*)(smc + TAL_OFF + boff) = lo;
        }
    }
    __syncthreads();

    uint32_t aRowOff = (uint32_t)((lane & 7) + ((g & 1) << 3));
    uint32_t aKOff   = (uint32_t)((g >> 1) << 4);
    uint32_t bPart272 = (uint32_t)(((lane & 7) + ((g >> 1) << 3)) * 272 + ((g & 1) << 4));
    uint32_t bPart144 = (uint32_t)(((lane & 7) + ((g >> 1) << 3)) * 144 + ((g & 1) << 4));

    float resA = 0.f, resB = 0.f;

    for (int br = 0; br < 2; br++) {
        float accF[16][4];
        #pragma unroll
        for (int q = 0; q < 16; q++)
            #pragma unroll
            for (int v = 0; v < 4; v++) accF[q][v] = 0.f;

        uint32_t aBaseRow = (uint32_t)(br * 128 + m0) + aRowOff;

        // prefetch chunk 0
        {
            uint32_t w1d = sb + W1B_OFF;
            for (int i = tid; i < 1024; i += 256) {
                int row = i >> 4, col = i & 15;
                CPA16(w1d + row * 272 + col * 16, (const char*)&g_w1h[0][0] + row * 256 + col * 16);
            }
            uint32_t w2d = sb + W2B_OFF;
            for (int i = tid; i < 1024; i += 256) {
                int row = i >> 3, col = i & 7;
                CPA16(w2d + row * 144 + col * 16, (const char*)&g_w2h[0][0] + row * 1024 + col * 16);
            }
            CPA_COMMIT();
        }

        for (int ch = 0; ch < 8; ch++) {
            if (ch < 7) {   // prefetch next chunk into other buffer
                int nc = ch + 1, nb = nc & 1;
                uint32_t w1d = sb + W1B_OFF + nb * 17408;
                const char* w1src = (const char*)&g_w1h[nc * 64][0];
                for (int i = tid; i < 1024; i += 256) {
                    int row = i >> 4, col = i & 15;
                    CPA16(w1d + row * 272 + col * 16, w1src + row * 256 + col * 16);
                }
                uint32_t w2d = sb + W2B_OFF + nb * 18432;
                const char* w2src = (const char*)&g_w2h[0][0] + nc * 128;
                for (int i = tid; i < 1024; i += 256) {
                    int row = i >> 3, col = i & 7;
                    CPA16(w2d + row * 144 + col * 16, w2src + row * 1024 + col * 16);
                }
                CPA_COMMIT();
                asm volatile("cp.async.wait_group 1;" ::: "memory");
            } else {
                asm volatile("cp.async.wait_group 0;" ::: "memory");
            }
            __syncthreads();

            int cb = ch & 1;
            // ---- GEMM1: h[16][64] = t(hi+lo)[16][128] @ W1ch^T ----
            float acc1[8][4];
            #pragma unroll
            for (int q = 0; q < 8; q++)
                #pragma unroll
                for (int v = 0; v < 4; v++) acc1[q][v] = 0.f;
            uint32_t aHi = sb + TAH_OFF + aBaseRow * 272u + aKOff;
            uint32_t aLo = sb + TAL_OFF + aBaseRow * 272u + aKOff;
            uint32_t w1b = sb + W1B_OFF + cb * 17408 + bPart272;
            #pragma unroll
            for (int k = 0; k < 8; k++) {
                uint32_t h0, h1, h2, h3, l0, l1, l2, l3;
                ldsm4(aHi + (uint32_t)k * 32u, h0, h1, h2, h3);
                ldsm4(aLo + (uint32_t)k * 32u, l0, l1, l2, l3);
                #pragma unroll
                for (int q = 0; q < 4; q++) {
                    uint32_t r0, r1, r2, r3;
                    ldsm4(w1b + (uint32_t)(q * 16 * 272) + (uint32_t)k * 32u, r0, r1, r2, r3);
                    mma_f16(acc1[2 * q],     h0, h1, h2, h3, r0, r1);
                    mma_f16(acc1[2 * q + 1], h0, h1, h2, h3, r2, r3);
                    mma_f16(acc1[2 * q],     l0, l1, l2, l3, r0, r1);
                    mma_f16(acc1[2 * q + 1], l0, l1, l2, l3, r2, r3);
                }
            }
            // ---- bias + relu + fp16 hi/lo split (registers only) ----
            uint32_t hh[8][2], hl[8][2];
            #pragma unroll
            for (int t = 0; t < 8; t++) {
                int cc = ch * 64 + t * 8 + ((lane & 3) << 1);
                float bb0 = b1s[cc], bb1 = b1s[cc + 1];
                float v0 = fmaxf(acc1[t][0] + bb0, 0.f);
                float v1 = fmaxf(acc1[t][1] + bb1, 0.f);
                float v2 = fmaxf(acc1[t][2] + bb0, 0.f);
                float v3 = fmaxf(acc1[t][3] + bb1, 0.f);
                __half q0 = __float2half_rn(v0), q1 = __float2half_rn(v1);
                __half q2 = __float2half_rn(v2), q3 = __float2half_rn(v3);
                hh[t][0] = pk2h(q0, q1);
                hh[t][1] = pk2h(q2, q3);
                hl[t][0] = pk2h(__float2half_rn(v0 - __half2float(q0)),
                                __float2half_rn(v1 - __half2float(q1)));
                hl[t][1] = pk2h(__float2half_rn(v2 - __half2float(q2)),
                                __float2half_rn(v3 - __half2float(q3)));
            }
            // ---- GEMM2: accF += h(hi+lo)[16][64] @ W2ch^T ----
            uint32_t w2b = sb + W2B_OFF + cb * 18432 + bPart144;
            #pragma unroll
            for (int ks = 0; ks < 4; ks++) {
                uint32_t ah0 = hh[2 * ks][0], ah1 = hh[2 * ks][1];
                uint32_t ah2 = hh[2 * ks + 1][0], ah3 = hh[2 * ks + 1][1];
                uint32_t al0 = hl[2 * ks][0], al1 = hl[2 * ks][1];
                uint32_t al2 = hl[2 * ks + 1][0], al3 = hl[2 * ks + 1][1];
                #pragma unroll
                for (int q = 0; q < 8; q++) {
                    uint32_t r0, r1, r2, r3;
                    ldsm4(w2b + (uint32_t)(q * 16 * 144) + (uint32_t)ks * 32u, r0, r1, r2, r3);
                    mma_f16(accF[2 * q],     ah0, ah1, ah2, ah3, r0, r1);
                    mma_f16(accF[2 * q + 1], ah0, ah1, ah2, ah3, r2, r3);
                    mma_f16(accF[2 * q],     al0, al1, al2, al3, r0, r1);
                    mma_f16(accF[2 * q + 1], al0, al1, al2, al3, r2, r3);
                }
            }
            __syncthreads();
        }

        // ---- epilogue: residual + fused LN2 + head ----
        float sA0 = 0.f, sA1 = 0.f, sA2 = 0.f, sB0 = 0.f, sB1 = 0.f, sB2 = 0.f;
        int ra = br * 128 + m0 + (lane >> 2);
        #pragma unroll
        for (int t = 0; t < 16; t++) {
            int c = t * 8 + ((lane & 3) << 1);
            uint32_t hia = *(const uint32_t*)(smc + TAH_OFF + ra * 272 + c * 2);
            uint32_t loa = *(const uint32_t*)(smc + TAL_OFF + ra * 272 + c * 2);
            uint32_t hib = *(const uint32_t*)(smc + TAH_OFF + (ra + 8) * 272 + c * 2);
            uint32_t lob = *(const uint32_t*)(smc + TAL_OFF + (ra + 8) * 272 + c * 2);
            float t0a = hLO(hia) + hLO(loa), t1a = hHI(hia) + hHI(loa);
            float t0b = hLO(hib) + hLO(lob), t1b = hHI(hib) + hHI(lob);
            float bz0 = b2s[c], bz1 = b2s[c + 1];
            float g0 = gws[br * 128 + c], g1 = gws[br * 128 + c + 1];
            float y0 = accF[t][0] + t0a + bz0;
            float y1 = accF[t][1] + t1a + bz1;
            float y2 = accF[t][2] + t0b + bz0;
            float y3 = accF[t][3] + t1b + bz1;
            sA0 += y0 + y1; sA1 += y0 * y0 + y1 * y1; sA2 += y0 * g0 + y1 * g1;
            sB0 += y2 + y3; sB1 += y2 * y2 + y3 * y3; sB2 += y2 * g0 + y3 * g1;
        }
        #pragma unroll
        for (int m = 1; m < 4; m <<= 1) {
            sA0 += __shfl_xor_sync(0xffffffffu, sA0, m);
            sA1 += __shfl_xor_sync(0xffffffffu, sA1, m);
            sA2 += __shfl_xor_sync(0xffffffffu, sA2, m);
            sB0 += __shfl_xor_sync(0xffffffffu, sB0, m);
            sB1 += __shfl_xor_sync(0xffffffffu, sB1, m);
            sB2 += __shfl_xor_sync(0xffffffffu, sB2, m);
        }
        float sgw = g_sc[br][0], cst = g_sc[br][1];
        float mean = sA0 * (1.f / 128.f);
        float var = sA1 * (1.f / 128.f) - mean * mean;
        resA += (sA2 - mean * sgw) * rsqrtf(var + 1e-5f) + cst;
        float meanb = sB0 * (1.f / 128.f);
        float varb = sB1 * (1.f / 128.f) - meanb * meanb;
        resB += (sB2 - meanb * sgw) * rsqrtf(varb + 1e-5f) + cst;
    }
    if ((lane & 3) == 0) {
        out[(size_t)tile * 128 + m0 + (lane >> 2)] = resA;
        out[(size_t)tile * 128 + m0 + 8 + (lane >> 2)] = resB;
    }
}

// ------------------------- launch -------------------------
extern "C" void kernel_launch(void* const* d_in, const int* in_sizes, int n_in,
                              void* d_out, int out_size) {
    const float* z    = (const float*)d_in[0];
    const float* fe   = (const float*)d_in[1];
    const float* inwp = (const float*)d_in[2];
    const float* inbp = (const float*)d_in[3];
    const float* outwp= (const float*)d_in[4];
    const float* outbp= (const float*)d_in[5];
    const float* inwf = (const float*)d_in[6];
    const float* inbf = (const float*)d_in[7];
    const float* outwf= (const float*)d_in[8];
    const float* outbf= (const float*)d_in[9];
    const float* ln1g = (const float*)d_in[10];
    const float* ln1b = (const float*)d_in[11];
    const float* w1   = (const float*)d_in[12];
    const float* b1   = (const float*)d_in[13];
    const float* w2   = (const float*)d_in[14];
    const float* b2   = (const float*)d_in[15];
    const float* ln2g = (const float*)d_in[16];
    const float* ln2b = (const float*)d_in[17];
    const float* oppw = (const float*)d_in[18];
    const float* oppb = (const float*)d_in[19];
    const float* opfw = (const float*)d_in[20];
    const float* opfb = (const float*)d_in[21];
    const float* alog = (const float*)d_in[22];
    const float* bp   = (const float*)d_in[23];
    const float* bf   = (const float*)d_in[24];

    int B = in_sizes[0] / Hx;
    int tiles = (B * Hx) / 128;
    cudaFuncSetAttribute(attn_k, cudaFuncAttributeMaxDynamicSharedMemorySize, K2_FLOATS * 4);
    cudaFuncSetAttribute(ffn_mma, cudaFuncAttributeMaxDynamicSharedMemorySize, SM3);

    pre_qkv<<<dim3(6, 8), 256>>>(fe, inwp, inwf);
    pre_misc<<<dim3(2, 8), 256>>>(inbp, inbf, outwp, outbp, outwf, outbf,
                                  ln2g, ln2b, oppw, oppb, opfw, opfb, alog, bp, bf);
    pre_wimg<<<256, 256>>>(w1, w2);
    attn_k<<<B / 4, 256, K2_FLOATS * 4>>>(z, fe, ln1g, ln1b);
    ffn_mma<<<tiles, 256, SM3>>>(b1, b2, (float*)d_out);
}

// round 8
// speedup vs baseline: 4.9563x; 1.3397x over previous
#include <cuda_runtime.h>
#include <cuda_fp16.h>
#include <math.h>
#include <stdint.h>

#define Hx 24
#define Dx 128
#define NHx 4
#define DHx 32
#define RS32 0.17677669529663687f

// ------------------------- device globals -------------------------
__device__ float g_E[2][3][Hx][Dx];
__device__ float g_G[2][NHx][Hx][Hx];
__device__ float g_Mk[2][NHx][Hx][Hx];
__device__ float g_gq[2][NHx][Hx];
__device__ float g_gk[2][NHx][Hx];
__device__ float g_P[2][NHx*Hx][Dx];
__device__ __align__(16) __half g_Ph[2][Dx][104];   // fp16 P transposed [c][k], padded
__device__ float g_Pc[2][Dx];
__device__ float g_gw[2][Dx];
__device__ float g_sc[2][2];
__device__ unsigned int g_t[2][25165824u];   // packed fp16 hi | lo<<16
__device__ __half g_w1h[512][128];
__device__ __half g_w2h[128][512];

// ------------------------- helpers -------------------------
__device__ __forceinline__ uint32_t cvta_s(const void* p) {
    uint32_t a;
    asm("{ .reg .u64 t; cvta.to.shared.u64 t, %1; cvt.u32.u64 %0, t; }" : "=r"(a) : "l"(p));
    return a;
}
__device__ __forceinline__ void ldsm4(uint32_t addr, uint32_t& r0, uint32_t& r1,
                                      uint32_t& r2, uint32_t& r3) {
    asm volatile("ldmatrix.sync.aligned.m8n8.x4.shared.b16 {%0,%1,%2,%3}, [%4];"
                 : "=r"(r0), "=r"(r1), "=r"(r2), "=r"(r3) : "r"(addr));
}
__device__ __forceinline__ void mma_f16(float d[4], uint32_t a0, uint32_t a1, uint32_t a2,
                                        uint32_t a3, uint32_t b0, uint32_t b1) {
    asm volatile("mma.sync.aligned.m16n8k16.row.col.f32.f16.f16.f32 "
                 "{%0,%1,%2,%3}, {%4,%5,%6,%7}, {%8,%9}, {%0,%1,%2,%3};"
                 : "+f"(d[0]), "+f"(d[1]), "+f"(d[2]), "+f"(d[3])
                 : "r"(a0), "r"(a1), "r"(a2), "r"(a3), "r"(b0), "r"(b1));
}
__device__ __forceinline__ uint32_t pk2h(__half e0, __half e1) {
    return (uint32_t)__half_as_ushort(e0) | ((uint32_t)__half_as_ushort(e1) << 16);
}
__device__ __forceinline__ float hLO(uint32_t v) {
    return __half2float(__ushort_as_half((unsigned short)(v & 0xFFFFu)));
}
__device__ __forceinline__ float hHI(uint32_t v) {
    return __half2float(__ushort_as_half((unsigned short)(v >> 16)));
}
#define CPA16(d, s) asm volatile("cp.async.cg.shared.global [%0], [%1], 16;" :: "r"(d), "l"(s))
#define CPA_COMMIT() asm volatile("cp.async.commit_group;" ::: "memory")

// ------------------------- precompute 1 -------------------------
__global__ void pre_qkv(const float* __restrict__ fe, const float* __restrict__ inwp,
                        const float* __restrict__ inwf) {
    int br = blockIdx.x / 3, which = blockIdx.x % 3;
    const float* W = (br ? inwf : inwp) + which * Dx * Dx;
    __shared__ float fes[Hx * Dx];
    for (int idx = threadIdx.x; idx < Hx * Dx; idx += 256) fes[idx] = fe[idx];
    __syncthreads();
    for (int idx = blockIdx.y * 256 + threadIdx.x; idx < Hx * Dx; idx += 2048) {
        int i = idx >> 7, c = idx & 127;
        float s = 0.f;
        #pragma unroll 8
        for (int d = 0; d < Dx; d++) s += fes[i * Dx + d] * W[c * Dx + d];
        g_E[br][which][i][c] = s;
    }
}

// ------------------------- precompute 2 -------------------------
__global__ void pre_misc(const float* __restrict__ inbp, const float* __restrict__ inbf,
                         const float* __restrict__ outwp, const float* __restrict__ outbp,
                         const float* __restrict__ outwf, const float* __restrict__ outbf,
                         const float* __restrict__ ln2g, const float* __restrict__ ln2b,
                         const float* __restrict__ oppw, const float* __restrict__ oppb,
                         const float* __restrict__ opfw, const float* __restrict__ opfb,
                         const float* __restrict__ alog,
                         const float* __restrict__ biasp, const float* __restrict__ biasf) {
    int br = blockIdx.x, gy = blockIdx.y;
    const float* inb  = br ? inbf  : inbp;
    const float* outw = br ? outwf : outwp;
    const float* outb = br ? outbf : outbp;
    const float* opw  = br ? opfw  : oppw;
    const float* opb  = br ? opfb  : oppb;
    const float* bias = br ? biasf : biasp;
    const float* qb = inb, *kb = inb + Dx, *vb = inb + 2 * Dx;
    __shared__ float g0s[NHx];
    int tid = threadIdx.x;
    if (tid < NHx) {
        float s = 0.f;
        for (int d = 0; d < DHx; d++) s += qb[tid * DHx + d] * kb[tid * DHx + d];
        g0s[tid] = s * RS32;
    }
    __syncthreads();
    int base = gy * 256 + tid;
    for (int idx = base; idx < NHx * Hx; idx += 2048) {
        int n = idx / Hx, i = idx % Hx;
        float s1 = 0.f, s2 = 0.f;
        for (int d = 0; d < DHx; d++) {
            s1 += g_E[br][0][i][n * DHx + d] * kb[n * DHx + d];
            s2 += g_E[br][1][i][n * DHx + d] * qb[n * DHx + d];
        }
        g_gq[br][n][i] = s1 * RS32;
        g_gk[br][n][i] = s2 * RS32;
    }
    for (int idx = base; idx < NHx * Hx * Hx; idx += 2048) {
        int n = idx / (Hx * Hx), i = (idx / Hx) % Hx, j = idx % Hx;
        float s = 0.f;
        for (int d = 0; d < DHx; d++)
            s += g_E[br][0][i][n * DHx + d] * g_E[br][1][j][n * DHx + d];
        g_G[br][n][i][j] = s * RS32;
        bool valid = (br == 0) ? (j <= i) : (j >= i);
        g_Mk[br][n][i][j] = valid ? bias[j - i + Hx - 1] + g0s[n] : -1e30f;
    }
    for (int idx = base; idx < NHx * Hx * Dx; idx += 2048) {
        int k = idx >> 7, c = idx & 127;
        int n = k / Hx, j = k % Hx;
        float s = 0.f;
        for (int d = 0; d < DHx; d++)
            s += outw[c * Dx + n * DHx + d] * g_E[br][2][j][n * DHx + d];
        g_P[br][k][c] = s;
        g_Ph[br][c][k] = __float2half_rn(s);
    }
    if (gy == 0) {
        float e0 = expf(alog[0]), e1 = expf(alog[1]);
        float alpha = (br == 0 ? e0 : e1) / (e0 + e1);
        for (int idx = tid; idx < Dx; idx += 256) {
            float s = outb[idx];
            for (int m = 0; m < Dx; m++) s += outw[idx * Dx + m] * vb[m];
            g_Pc[br][idx] = s;
            g_gw[br][idx] = ln2g[idx] * opw[idx] * alpha;
        }
        __syncthreads();
        __threadfence();
        if (tid == 0) {
            float sgw = 0.f, cst = 0.f;
            for (int c = 0; c < Dx; c++) { sgw += g_gw[br][c]; cst += ln2b[c] * opw[c]; }
            g_sc[br][0] = sgw;
            g_sc[br][1] = alpha * (cst + opb[0]);
        }
    }
}

// ------------------------- precompute 3: fp16 weight images -------------------------
__global__ void pre_wimg(const float* __restrict__ w1, const float* __restrict__ w2) {
    int idx = blockIdx.x * 256 + threadIdx.x;
    if (idx >= 65536) return;
    {
        int f = idx >> 7, c = idx & 127;
        g_w1h[f][c] = __float2half_rn(w1[idx]);
    }
    {
        int n = idx >> 9, ff = idx & 511;
        g_w2h[n][ff] = __float2half_rn(w2[idx]);
    }
}

// ------------------------- K2: attention (mma.sync) + LN1 -> packed fp16 t ----------
// smem floats: zsm@0(96) c1g@96(128) c1b@224(128) pcs@352(128) fesm@480(24*133=3192)
//              Wh@3672 (96x104 half = 4992 f)  Ph@8664 (128x104 half = 6656 f)
// total = 15320 floats = 61280 BYTES
#define FE0 480
#define WH0 3672
#define PH0 8664
#define K2BYTES 61280

__global__ __launch_bounds__(256)
void attn_k(const float* __restrict__ z, const float* __restrict__ fe,
            const float* __restrict__ ln1g, const float* __restrict__ ln1b) {
    extern __shared__ float sm[];
    float* zsm  = sm;
    float* c1g  = sm + 96;
    float* c1b  = sm + 224;
    float* pcs  = sm + 352;
    float* fesm = sm + FE0;
    __half* Wh  = (__half*)(sm + WH0);
    uint32_t sb = cvta_s(sm);
    uint32_t WhB = sb + WH0 * 4;
    uint32_t PhB = sb + PH0 * 4;
    int tid = threadIdx.x, wid = tid >> 5, lane = tid & 31;
    int g = lane >> 3;
    int blk = blockIdx.x;

    if (tid < 96) zsm[tid] = z[blk * 96 + tid];
    if (tid >= 128) { c1g[tid - 128] = ln1g[tid - 128]; c1b[tid - 128] = ln1b[tid - 128]; }
    for (int idx = tid; idx < Hx * Dx; idx += 256)
        fesm[(idx >> 7) * 133 + (idx & 127)] = fe[idx];
    __syncthreads();

    for (int br = 0; br < 2; br++) {
        // stage Ph (flat uint4 copy: smem layout == global layout) + Pc
        {
            const uint4* ps = (const uint4*)&g_Ph[br][0][0];
            uint4* pd = (uint4*)(sm + PH0);
            for (int i = tid; i < 1664; i += 256) pd[i] = ps[i];
            if (tid < 128) pcs[tid] = g_Pc[br][tid];
        }
        // softmax + weight fold -> fp16 W
        for (int rs = tid; rs < 384; rs += 256) {
            int bb = rs / 96, rem = rs % 96, n = rem / 24, i = rem % 24;
            float zi = zsm[bb * 24 + i];
            const float* Gp = &g_G[br][n][i][0];
            const float* Mp = &g_Mk[br][n][i][0];
            const float* gkp = &g_gk[br][n][0];
            float gq = g_gq[br][n][i];
            float s[24]; float mx = -1e30f;
            #pragma unroll
            for (int j = 0; j < 24; j++) {
                float zj = zsm[bb * 24 + j];
                float v = zi * zj * Gp[j] + zi * gq + zj * gkp[j] + Mp[j];
                s[j] = v; mx = fmaxf(mx, v);
            }
            float sum = 0.f;
            #pragma unroll
            for (int j = 0; j < 24; j++) { s[j] = __expf(fmaxf(s[j] - mx, -80.f)); sum += s[j]; }
            float inv = 1.f / sum;
            __half* wrow = &Wh[(bb * 24 + i) * 104 + n * 24];
            #pragma unroll
            for (int j = 0; j < 24; j++)
                wrow[j] = __float2half_rn(s[j] * inv * zsm[bb * 24 + j]);
        }
        __syncthreads();

        if (wid < 6) {
            // GEMM: o[16x128] = W[16x96] @ P^T ; per warp, mma.sync fp16
            float accO[16][4];
            #pragma unroll
            for (int q = 0; q < 16; q++)
                #pragma unroll
                for (int v = 0; v < 4; v++) accO[q][v] = 0.f;
            uint32_t aAddr = WhB + (uint32_t)(wid * 16 + (lane & 7) + ((g & 1) << 3)) * 208u
                                 + (uint32_t)((g >> 1) << 4);
            uint32_t bAddr = PhB + (uint32_t)((lane & 7) + ((g >> 1) << 3)) * 208u
                                 + (uint32_t)((g & 1) << 4);
            #pragma unroll
            for (int k = 0; k < 6; k++) {
                uint32_t a0, a1, a2, a3;
                ldsm4(aAddr + (uint32_t)k * 32u, a0, a1, a2, a3);
                #pragma unroll
                for (int q = 0; q < 8; q++) {
                    uint32_t r0, r1, r2, r3;
                    ldsm4(bAddr + (uint32_t)(q * 16 * 208) + (uint32_t)k * 32u, r0, r1, r2, r3);
                    mma_f16(accO[2 * q],     a0, a1, a2, a3, r0, r1);
                    mma_f16(accO[2 * q + 1], a0, a1, a2, a3, r2, r3);
                }
            }
            // epilogue: + Pc + tokens, LN1, pack fp16 hi/lo, store
            int ra = wid * 16 + (lane >> 2);
            int rb = ra + 8;
            int iiA = ra % 24, iiB = rb % 24;
            float zA = zsm[ra], zB = zsm[rb];
            float sA0 = 0.f, sA1 = 0.f, sB0 = 0.f, sB1 = 0.f;
            #pragma unroll
            for (int t = 0; t < 16; t++) {
                int c = t * 8 + ((lane & 3) << 1);
                float pc0 = pcs[c], pc1 = pcs[c + 1];
                float y0 = accO[t][0] + pc0 + zA * fesm[iiA * 133 + c];
                float y1 = accO[t][1] + pc1 + zA * fesm[iiA * 133 + c + 1];
                float y2 = accO[t][2] + pc0 + zB * fesm[iiB * 133 + c];
                float y3 = accO[t][3] + pc1 + zB * fesm[iiB * 133 + c + 1];
                accO[t][0] = y0; accO[t][1] = y1; accO[t][2] = y2; accO[t][3] = y3;
                sA0 += y0 + y1; sA1 += y0 * y0 + y1 * y1;
                sB0 += y2 + y3; sB1 += y2 * y2 + y3 * y3;
            }
            #pragma unroll
            for (int m = 1; m < 4; m <<= 1) {
                sA0 += __shfl_xor_sync(0xffffffffu, sA0, m);
                sA1 += __shfl_xor_sync(0xffffffffu, sA1, m);
                sB0 += __shfl_xor_sync(0xffffffffu, sB0, m);
                sB1 += __shfl_xor_sync(0xffffffffu, sB1, m);
            }
            float mA = sA0 * (1.f / 128.f);
            float rA = rsqrtf(sA1 * (1.f / 128.f) - mA * mA + 1e-5f);
            float mB = sB0 * (1.f / 128.f);
            float rB = rsqrtf(sB1 * (1.f / 128.f) - mB * mB + 1e-5f);
            unsigned int* dstA = &g_t[br][(size_t)(blk * 96 + ra) * 128];
            unsigned int* dstB = &g_t[br][(size_t)(blk * 96 + rb) * 128];
            #pragma unroll
            for (int t = 0; t < 16; t++) {
                int c = t * 8 + ((lane & 3) << 1);
                float g0 = c1g[c], g1 = c1g[c + 1], b0 = c1b[c], b1 = c1b[c + 1];
                float tA0 = (accO[t][0] - mA) * rA * g0 + b0;
                float tA1 = (accO[t][1] - mA) * rA * g1 + b1;
                float tB0 = (accO[t][2] - mB) * rB * g0 + b0;
                float tB1 = (accO[t][3] - mB) * rB * g1 + b1;
                __half hA0 = __float2half_rn(tA0), hA1 = __float2half_rn(tA1);
                __half hB0 = __float2half_rn(tB0), hB1 = __float2half_rn(tB1);
                uint2 vA, vB;
                vA.x = pk2h(hA0, __float2half_rn(tA0 - __half2float(hA0)));
                vA.y = pk2h(hA1, __float2half_rn(tA1 - __half2float(hA1)));
                vB.x = pk2h(hB0, __float2half_rn(tB0 - __half2float(hB0)));
                vB.y = pk2h(hB1, __float2half_rn(tB1 - __half2float(hB1)));
                *(uint2*)&dstA[c] = vA;
                *(uint2*)&dstB[c] = vB;
            }
        }
        __syncthreads();
    }
}

// ------------------------- K3: FFN fp16 x2, 512 threads, both branches ------------
#define TAH_OFF 0
#define TAL_OFF 69632
#define W1B_OFF 139264   /* 2 x 17408 */
#define W2B_OFF 174080   /* 2 x 18432 */
#define B1S_OFF 210944
#define GWS_OFF 212992
#define B2S_OFF 214016
#define OAC_OFF 214528
#define SM3 215040

__global__ __launch_bounds__(512, 1)
void ffn_mma(const float* __restrict__ b1g, const float* __restrict__ b2g,
             float* __restrict__ out) {
    extern __shared__ char smc[];
    uint32_t sb = cvta_s(smc);
    int tid = threadIdx.x, wid = tid >> 5, lane = tid & 31;
    int tile = blockIdx.x;
    int g = lane >> 3;
    int br = wid >> 3;
    int m0 = (wid & 7) * 16;

    float* b1s = (float*)(smc + B1S_OFF);
    float* gws = (float*)(smc + GWS_OFF);
    float* b2s = (float*)(smc + B2S_OFF);
    float* oac = (float*)(smc + OAC_OFF);
    if (tid < 512) b1s[tid] = b1g[tid];
    if (tid < 256) gws[tid] = ((const float*)g_gw)[tid];
    else if (tid < 384) b2s[tid - 256] = b2g[tid - 256];

    // stage t tile (both branches): unpack fp16 hi/lo into padded rows
    for (int b2 = 0; b2 < 2; b2++) {
        const uint2* src = (const uint2*)&g_t[b2][(size_t)tile * 16384];
        for (int idx = tid; idx < 8192; idx += 512) {
            uint2 v = src[idx];
            int r = idx >> 6, pr = idx & 63;
            uint32_t hi = (v.x & 0xFFFFu) | (v.y << 16);
            uint32_t lo = (v.x >> 16) | (v.y & 0xFFFF0000u);
            uint32_t boff = (uint32_t)(b2 * 128 + r) * 272u + (uint32_t)pr * 4u;
            *(uint32_t*)(smc + TAH_OFF + boff) = hi;
            *(uint32_t*)(smc + TAL_OFF + boff) = lo;
        }
    }

    // prefetch chunk 0
    {
        uint32_t w1d = sb + W1B_OFF;
        for (int i = tid; i < 1024; i += 512) {
            int row = i >> 4, col = i & 15;
            CPA16(w1d + row * 272 + col * 16, (const char*)&g_w1h[0][0] + row * 256 + col * 16);
        }
        uint32_t w2d = sb + W2B_OFF;
        for (int i = tid; i < 1024; i += 512) {
            int row = i >> 3, col = i & 7;
            CPA16(w2d + row * 144 + col * 16, (const char*)&g_w2h[0][0] + row * 1024 + col * 16);
        }
        CPA_COMMIT();
    }
    __syncthreads();

    uint32_t aRowOff = (uint32_t)((lane & 7) + ((g & 1) << 3));
    uint32_t aKOff   = (uint32_t)((g >> 1) << 4);
    uint32_t bPart272 = (uint32_t)(((lane & 7) + ((g >> 1) << 3)) * 272 + ((g & 1) << 4));
    uint32_t bPart144 = (uint32_t)(((lane & 7) + ((g >> 1) << 3)) * 144 + ((g & 1) << 4));
    uint32_t aBaseRow = (uint32_t)(br * 128 + m0) + aRowOff;

    float accF[16][4];
    #pragma unroll
    for (int q = 0; q < 16; q++)
        #pragma unroll
        for (int v = 0; v < 4; v++) accF[q][v] = 0.f;

    for (int ch = 0; ch < 8; ch++) {
        if (ch < 7) {
            int nc = ch + 1, nb = nc & 1;
            uint32_t w1d = sb + W1B_OFF + nb * 17408;
            const char* w1src = (const char*)&g_w1h[nc * 64][0];
            for (int i = tid; i < 1024; i += 512) {
                int row = i >> 4, col = i & 15;
                CPA16(w1d + row * 272 + col * 16, w1src + row * 256 + col * 16);
            }
            uint32_t w2d = sb + W2B_OFF + nb * 18432;
            const char* w2src = (const char*)&g_w2h[0][0] + nc * 128;
            for (int i = tid; i < 1024; i += 512) {
                int row = i >> 3, col = i & 7;
                CPA16(w2d + row * 144 + col * 16, w2src + row * 1024 + col * 16);
            }
            CPA_COMMIT();
            asm volatile("cp.async.wait_group 1;" ::: "memory");
        } else {
            asm volatile("cp.async.wait_group 0;" ::: "memory");
        }
        __syncthreads();

        int cb = ch & 1;
        // ---- GEMM1: h[16][64] = t(hi+lo)[16][128] @ W1ch^T ----
        float acc1[8][4];
        #pragma unroll
        for (int q = 0; q < 8; q++)
            #pragma unroll
            for (int v = 0; v < 4; v++) acc1[q][v] = 0.f;
        uint32_t aHi = sb + TAH_OFF + aBaseRow * 272u + aKOff;
        uint32_t aLo = sb + TAL_OFF + aBaseRow * 272u + aKOff;
        uint32_t w1b = sb + W1B_OFF + cb * 17408 + bPart272;
        #pragma unroll
        for (int k = 0; k < 8; k++) {
            uint32_t h0, h1, h2, h3, l0, l1, l2, l3;
            ldsm4(aHi + (uint32_t)k * 32u, h0, h1, h2, h3);
            ldsm4(aLo + (uint32_t)k * 32u, l0, l1, l2, l3);
            #pragma unroll
            for (int q = 0; q < 4; q++) {
                uint32_t r0, r1, r2, r3;
                ldsm4(w1b + (uint32_t)(q * 16 * 272) + (uint32_t)k * 32u, r0, r1, r2, r3);
                mma_f16(acc1[2 * q],     h0, h1, h2, h3, r0, r1);
                mma_f16(acc1[2 * q + 1], h0, h1, h2, h3, r2, r3);
                mma_f16(acc1[2 * q],     l0, l1, l2, l3, r0, r1);
                mma_f16(acc1[2 * q + 1], l0, l1, l2, l3, r2, r3);
            }
        }
        // ---- GEMM2 with fused bias/relu/split per ks ----
        uint32_t w2b = sb + W2B_OFF + cb * 18432 + bPart144;
        #pragma unroll
        for (int ks = 0; ks < 4; ks++) {
            uint32_t ah0, ah1, ah2, ah3, al0, al1, al2, al3;
            {
                int t0i = 2 * ks, t1i = 2 * ks + 1;
                int cc0 = ch * 64 + t0i * 8 + ((lane & 3) << 1);
                int cc1 = ch * 64 + t1i * 8 + ((lane & 3) << 1);
                float b00 = b1s[cc0], b01 = b1s[cc0 + 1];
                float b10 = b1s[cc1], b11 = b1s[cc1 + 1];
                float v0 = fmaxf(acc1[t0i][0] + b00, 0.f);
                float v1 = fmaxf(acc1[t0i][1] + b01, 0.f);
                float v2 = fmaxf(acc1[t0i][2] + b00, 0.f);
                float v3 = fmaxf(acc1[t0i][3] + b01, 0.f);
                float w0 = fmaxf(acc1[t1i][0] + b10, 0.f);
                float w1 = fmaxf(acc1[t1i][1] + b11, 0.f);
                float w2 = fmaxf(acc1[t1i][2] + b10, 0.f);
                float w3 = fmaxf(acc1[t1i][3] + b11, 0.f);
                __half q0 = __float2half_rn(v0), q1 = __float2half_rn(v1);
                __half q2 = __float2half_rn(v2), q3 = __float2half_rn(v3);
                __half p0 = __float2half_rn(w0), p1 = __float2half_rn(w1);
                __half p2 = __float2half_rn(w2), p3 = __float2half_rn(w3);
                ah0 = pk2h(q0, q1); ah1 = pk2h(q2, q3);
                ah2 = pk2h(p0, p1); ah3 = pk2h(p2, p3);
                al0 = pk2h(__float2half_rn(v0 - __half2float(q0)), __float2half_rn(v1 - __half2float(q1)));
                al1 = pk2h(__float2half_rn(v2 - __half2float(q2)), __float2half_rn(v3 - __half2float(q3)));
                al2 = pk2h(__float2half_rn(w0 - __half2float(p0)), __float2half_rn(w1 - __half2float(p1)));
                al3 = pk2h(__float2half_rn(w2 - __half2float(p2)), __float2half_rn(w3 - __half2float(p3)));
            }
            #pragma unroll
            for (int q = 0; q < 8; q++) {
                uint32_t r0, r1, r2, r3;
                ldsm4(w2b + (uint32_t)(q * 16 * 144) + (uint32_t)ks * 32u, r0, r1, r2, r3);
                mma_f16(accF[2 * q],     ah0, ah1, ah2, ah3, r0, r1);
                mma_f16(accF[2 * q + 1], ah0, ah1, ah2, ah3, r2, r3);
                mma_f16(accF[2 * q],     al0, al1, al2, al3, r0, r1);
                mma_f16(accF[2 * q + 1], al0, al1, al2, al3, r2, r3);
            }
        }
        __syncthreads();
    }

    // ---- epilogue: residual + fused LN2 + head ----
    float sA0 = 0.f, sA1 = 0.f, sA2 = 0.f, sB0 = 0.f, sB1 = 0.f, sB2 = 0.f;
    int ra = br * 128 + m0 + (lane >> 2);
    #pragma unroll
    for (int t = 0; t < 16; t++) {
        int c = t * 8 + ((lane & 3) << 1);
        uint32_t hia = *(const uint32_t*)(smc + TAH_OFF + ra * 272 + c * 2);
        uint32_t loa = *(const uint32_t*)(smc + TAL_OFF + ra * 272 + c * 2);
        uint32_t hib = *(const uint32_t*)(smc + TAH_OFF + (ra + 8) * 272 + c * 2);
        uint32_t lob = *(const uint32_t*)(smc + TAL_OFF + (ra + 8) * 272 + c * 2);
        float t0a = hLO(hia) + hLO(loa), t1a = hHI(hia) + hHI(loa);
        float t0b = hLO(hib) + hLO(lob), t1b = hHI(hib) + hHI(lob);
        float bz0 = b2s[c], bz1 = b2s[c + 1];
        float g0 = gws[br * 128 + c], g1 = gws[br * 128 + c + 1];
        float y0 = accF[t][0] + t0a + bz0;
        float y1 = accF[t][1] + t1a + bz1;
        float y2 = accF[t][2] + t0b + bz0;
        float y3 = accF[t][3] + t1b + bz1;
        sA0 += y0 + y1; sA1 += y0 * y0 + y1 * y1; sA2 += y0 * g0 + y1 * g1;
        sB0 += y2 + y3; sB1 += y2 * y2 + y3 * y3; sB2 += y2 * g0 + y3 * g1;
    }
    #pragma unroll
    for (int m = 1; m < 4; m <<= 1) {
        sA0 += __shfl_xor_sync(0xffffffffu, sA0, m);
        sA1 += __shfl_xor_sync(0xffffffffu, sA1, m);
        sA2 += __shfl_xor_sync(0xffffffffu, sA2, m);
        sB0 += __shfl_xor_sync(0xffffffffu, sB0, m);
        sB1 += __shfl_xor_sync(0xffffffffu, sB1, m);
        sB2 += __shfl_xor_sync(0xffffffffu, sB2, m);
    }
    float sgw = g_sc[br][0], cst = g_sc[br][1];
    float mean = sA0 * (1.f / 128.f);
    float var = sA1 * (1.f / 128.f) - mean * mean;
    float resA = (sA2 - mean * sgw) * rsqrtf(var + 1e-5f) + cst;
    float meanb = sB0 * (1.f / 128.f);
    float varb = sB1 * (1.f / 128.f) - meanb * meanb;
    float resB = (sB2 - meanb * sgw) * rsqrtf(varb + 1e-5f) + cst;

    if (br == 0 && (lane & 3) == 0) {
        oac[m0 + (lane >> 2)] = resA;
        oac[m0 + 8 + (lane >> 2)] = resB;
    }
    __syncthreads();
    if (br == 1 && (lane & 3) == 0) {
        out[(size_t)tile * 128 + m0 + (lane >> 2)] = oac[m0 + (lane >> 2)] + resA;
        out[(size_t)tile * 128 + m0 + 8 + (lane >> 2)] = oac[m0 + 8 + (lane >> 2)] + resB;
    }
}

// ------------------------- launch -------------------------
extern "C" void kernel_launch(void* const* d_in, const int* in_sizes, int n_in,
                              void* d_out, int out_size) {
    const float* z    = (const float*)d_in[0];
    const float* fe   = (const float*)d_in[1];
    const float* inwp = (const float*)d_in[2];
    const float* inbp = (const float*)d_in[3];
    const float* outwp= (const float*)d_in[4];
    const float* outbp= (const float*)d_in[5];
    const float* inwf = (const float*)d_in[6];
    const float* inbf = (const float*)d_in[7];
    const float* outwf= (const float*)d_in[8];
    const float* outbf= (const float*)d_in[9];
    const float* ln1g = (const float*)d_in[10];
    const float* ln1b = (const float*)d_in[11];
    const float* w1   = (const float*)d_in[12];
    const float* b1   = (const float*)d_in[13];
    const float* w2   = (const float*)d_in[14];
    const float* b2   = (const float*)d_in[15];
    const float* ln2g = (const float*)d_in[16];
    const float* ln2b = (const float*)d_in[17];
    const float* oppw = (const float*)d_in[18];
    const float* oppb = (const float*)d_in[19];
    const float* opfw = (const float*)d_in[20];
    const float* opfb = (const float*)d_in[21];
    const float* alog = (const float*)d_in[22];
    const float* bp   = (const float*)d_in[23];
    const float* bf   = (const float*)d_in[24];

    int B = in_sizes[0] / Hx;
    int tiles = (B * Hx) / 128;
    cudaFuncSetAttribute(attn_k, cudaFuncAttributeMaxDynamicSharedMemorySize, K2BYTES);
    cudaFuncSetAttribute(ffn_mma, cudaFuncAttributeMaxDynamicSharedMemorySize, SM3);

    pre_qkv<<<dim3(6, 8), 256>>>(fe, inwp, inwf);
    pre_misc<<<dim3(2, 8), 256>>>(inbp, inbf, outwp, outbp, outwf, outbf,
                                  ln2g, ln2b, oppw, oppb, opfw, opfb, alog, bp, bf);
    pre_wimg<<<256, 256>>>(w1, w2);
    attn_k<<<B / 4, 256, K2BYTES>>>(z, fe, ln1g, ln1b);
    ffn_mma<<<tiles, 512, SM3>>>(b1, b2, (float*)d_out);
}

// round 9
// speedup vs baseline: 6.3313x; 1.2774x over previous
#include <cuda_runtime.h>
#include <cuda_fp16.h>
#include <math.h>
#include <stdint.h>

#define Hx 24
#define Dx 128
#define NHx 4
#define DHx 32
#define RS32 0.17677669529663687f

// ------------------------- device globals -------------------------
__device__ float g_E[2][3][Hx][Dx];
__device__ float g_G[2][NHx][Hx][Hx];
__device__ float g_Mk[2][NHx][Hx][Hx];
__device__ float g_gq[2][NHx][Hx];
__device__ float g_gk[2][NHx][Hx];
__device__ float g_P[2][NHx*Hx][Dx];
__device__ __align__(16) __half g_Ph[2][Dx][104];   // fp16 P transposed [c][k], padded
__device__ float g_Pc[2][Dx];
__device__ float g_gw[2][Dx];
__device__ float g_sc[2][2];
__device__ unsigned int g_t[2][25165824u];   // packed fp16 hi | lo<<16
__device__ __half g_w1h[512][128];
__device__ __half g_w2h[128][512];

// ------------------------- helpers -------------------------
__device__ __forceinline__ uint32_t cvta_s(const void* p) {
    uint32_t a;
    asm("{ .reg .u64 t; cvta.to.shared.u64 t, %1; cvt.u32.u64 %0, t; }" : "=r"(a) : "l"(p));
    return a;
}
__device__ __forceinline__ void ldsm4(uint32_t addr, uint32_t& r0, uint32_t& r1,
                                      uint32_t& r2, uint32_t& r3) {
    asm volatile("ldmatrix.sync.aligned.m8n8.x4.shared.b16 {%0,%1,%2,%3}, [%4];"
                 : "=r"(r0), "=r"(r1), "=r"(r2), "=r"(r3) : "r"(addr));
}
__device__ __forceinline__ void mma_f16(float d[4], uint32_t a0, uint32_t a1, uint32_t a2,
                                        uint32_t a3, uint32_t b0, uint32_t b1) {
    asm volatile("mma.sync.aligned.m16n8k16.row.col.f32.f16.f16.f32 "
                 "{%0,%1,%2,%3}, {%4,%5,%6,%7}, {%8,%9}, {%0,%1,%2,%3};"
                 : "+f"(d[0]), "+f"(d[1]), "+f"(d[2]), "+f"(d[3])
                 : "r"(a0), "r"(a1), "r"(a2), "r"(a3), "r"(b0), "r"(b1));
}
__device__ __forceinline__ uint32_t pk2h(__half e0, __half e1) {
    return (uint32_t)__half_as_ushort(e0) | ((uint32_t)__half_as_ushort(e1) << 16);
}
__device__ __forceinline__ float hLO(uint32_t v) {
    return __half2float(__ushort_as_half((unsigned short)(v & 0xFFFFu)));
}
__device__ __forceinline__ float hHI(uint32_t v) {
    return __half2float(__ushort_as_half((unsigned short)(v >> 16)));
}
#define CPA16(d, s) asm volatile("cp.async.cg.shared.global [%0], [%1], 16;" :: "r"(d), "l"(s))
#define CPA_COMMIT() asm volatile("cp.async.commit_group;" ::: "memory")

// ------------------------- precompute 1 -------------------------
__global__ void pre_qkv(const float* __restrict__ fe, const float* __restrict__ inwp,
                        const float* __restrict__ inwf) {
    int br = blockIdx.x / 3, which = blockIdx.x % 3;
    const float* W = (br ? inwf : inwp) + which * Dx * Dx;
    __shared__ float fes[Hx * Dx];
    for (int idx = threadIdx.x; idx < Hx * Dx; idx += 256) fes[idx] = fe[idx];
    __syncthreads();
    for (int idx = blockIdx.y * 256 + threadIdx.x; idx < Hx * Dx; idx += 2048) {
        int i = idx >> 7, c = idx & 127;
        float s = 0.f;
        #pragma unroll 8
        for (int d = 0; d < Dx; d++) s += fes[i * Dx + d] * W[c * Dx + d];
        g_E[br][which][i][c] = s;
    }
}

// ------------------------- precompute 2 -------------------------
__global__ void pre_misc(const float* __restrict__ inbp, const float* __restrict__ inbf,
                         const float* __restrict__ outwp, const float* __restrict__ outbp,
                         const float* __restrict__ outwf, const float* __restrict__ outbf,
                         const float* __restrict__ ln2g, const float* __restrict__ ln2b,
                         const float* __restrict__ oppw, const float* __restrict__ oppb,
                         const float* __restrict__ opfw, const float* __restrict__ opfb,
                         const float* __restrict__ alog,
                         const float* __restrict__ biasp, const float* __restrict__ biasf) {
    int br = blockIdx.x, gy = blockIdx.y;
    const float* inb  = br ? inbf  : inbp;
    const float* outw = br ? outwf : outwp;
    const float* outb = br ? outbf : outbp;
    const float* opw  = br ? opfw  : oppw;
    const float* opb  = br ? opfb  : oppb;
    const float* bias = br ? biasf : biasp;
    const float* qb = inb, *kb = inb + Dx, *vb = inb + 2 * Dx;
    __shared__ float g0s[NHx];
    int tid = threadIdx.x;
    if (tid < NHx) {
        float s = 0.f;
        for (int d = 0; d < DHx; d++) s += qb[tid * DHx + d] * kb[tid * DHx + d];
        g0s[tid] = s * RS32;
    }
    __syncthreads();
    int base = gy * 256 + tid;
    for (int idx = base; idx < NHx * Hx; idx += 2048) {
        int n = idx / Hx, i = idx % Hx;
        float s1 = 0.f, s2 = 0.f;
        for (int d = 0; d < DHx; d++) {
            s1 += g_E[br][0][i][n * DHx + d] * kb[n * DHx + d];
            s2 += g_E[br][1][i][n * DHx + d] * qb[n * DHx + d];
        }
        g_gq[br][n][i] = s1 * RS32;
        g_gk[br][n][i] = s2 * RS32;
    }
    for (int idx = base; idx < NHx * Hx * Hx; idx += 2048) {
        int n = idx / (Hx * Hx), i = (idx / Hx) % Hx, j = idx % Hx;
        float s = 0.f;
        for (int d = 0; d < DHx; d++)
            s += g_E[br][0][i][n * DHx + d] * g_E[br][1][j][n * DHx + d];
        g_G[br][n][i][j] = s * RS32;
        bool valid = (br == 0) ? (j <= i) : (j >= i);
        g_Mk[br][n][i][j] = valid ? bias[j - i + Hx - 1] + g0s[n] : -1e30f;
    }
    for (int idx = base; idx < NHx * Hx * Dx; idx += 2048) {
        int k = idx >> 7, c = idx & 127;
        int n = k / Hx, j = k % Hx;
        float s = 0.f;
        for (int d = 0; d < DHx; d++)
            s += outw[c * Dx + n * DHx + d] * g_E[br][2][j][n * DHx + d];
        g_P[br][k][c] = s;
        g_Ph[br][c][k] = __float2half_rn(s);
    }
    if (gy == 0) {
        float e0 = expf(alog[0]), e1 = expf(alog[1]);
        float alpha = (br == 0 ? e0 : e1) / (e0 + e1);
        for (int idx = tid; idx < Dx; idx += 256) {
            float s = outb[idx];
            for (int m = 0; m < Dx; m++) s += outw[idx * Dx + m] * vb[m];
            g_Pc[br][idx] = s;
            g_gw[br][idx] = ln2g[idx] * opw[idx] * alpha;
        }
        __syncthreads();
        __threadfence();
        if (tid == 0) {
            float sgw = 0.f, cst = 0.f;
            for (int c = 0; c < Dx; c++) { sgw += g_gw[br][c]; cst += ln2b[c] * opw[c]; }
            g_sc[br][0] = sgw;
            g_sc[br][1] = alpha * (cst + opb[0]);
        }
    }
}

// ------------------------- precompute 3: fp16 weight images -------------------------
__global__ void pre_wimg(const float* __restrict__ w1, const float* __restrict__ w2) {
    int idx = blockIdx.x * 256 + threadIdx.x;
    if (idx >= 65536) return;
    {
        int f = idx >> 7, c = idx & 127;
        g_w1h[f][c] = __float2half_rn(w1[idx]);
    }
    {
        int n = idx >> 9, ff = idx & 511;
        g_w2h[n][ff] = __float2half_rn(w2[idx]);
    }
}

// ------------------------- K2: attention (mma.sync) + LN1 -> packed fp16 t ----------
#define FE0 480
#define WH0 3672
#define PH0 8664
#define K2BYTES 61280

__global__ __launch_bounds__(256)
void attn_k(const float* __restrict__ z, const float* __restrict__ fe,
            const float* __restrict__ ln1g, const float* __restrict__ ln1b) {
    extern __shared__ float sm[];
    float* zsm  = sm;
    float* c1g  = sm + 96;
    float* c1b  = sm + 224;
    float* pcs  = sm + 352;
    float* fesm = sm + FE0;
    __half* Wh  = (__half*)(sm + WH0);
    uint32_t sb = cvta_s(sm);
    uint32_t WhB = sb + WH0 * 4;
    uint32_t PhB = sb + PH0 * 4;
    int tid = threadIdx.x, wid = tid >> 5, lane = tid & 31;
    int g = lane >> 3;
    int blk = blockIdx.x;

    if (tid < 96) zsm[tid] = z[blk * 96 + tid];
    if (tid >= 128) { c1g[tid - 128] = ln1g[tid - 128]; c1b[tid - 128] = ln1b[tid - 128]; }
    for (int idx = tid; idx < Hx * Dx; idx += 256)
        fesm[(idx >> 7) * 133 + (idx & 127)] = fe[idx];
    __syncthreads();

    for (int br = 0; br < 2; br++) {
        // stage Ph + Pc
        {
            const uint4* ps = (const uint4*)&g_Ph[br][0][0];
            uint4* pd = (uint4*)(sm + PH0);
            for (int i = tid; i < 1664; i += 256) pd[i] = ps[i];
            if (tid < 128) pcs[tid] = g_Pc[br][tid];
        }
        // softmax + weight fold -> fp16 W
        for (int rs = tid; rs < 384; rs += 256) {
            int bb = rs / 96, rem = rs % 96, n = rem / 24, i = rem % 24;
            float zi = zsm[bb * 24 + i];
            const float* Gp = &g_G[br][n][i][0];
            const float* Mp = &g_Mk[br][n][i][0];
            const float* gkp = &g_gk[br][n][0];
            float gq = g_gq[br][n][i];
            float s[24]; float mx = -1e30f;
            #pragma unroll
            for (int j = 0; j < 24; j++) {
                float zj = zsm[bb * 24 + j];
                float v = zi * zj * Gp[j] + zi * gq + zj * gkp[j] + Mp[j];
                s[j] = v; mx = fmaxf(mx, v);
            }
            float sum = 0.f;
            #pragma unroll
            for (int j = 0; j < 24; j++) { s[j] = __expf(fmaxf(s[j] - mx, -80.f)); sum += s[j]; }
            float inv = 1.f / sum;
            __half* wrow = &Wh[(bb * 24 + i) * 104 + n * 24];
            #pragma unroll
            for (int j = 0; j < 24; j++)
                wrow[j] = __float2half_rn(s[j] * inv * zsm[bb * 24 + j]);
        }
        __syncthreads();

        if (wid < 6) {
            // GEMM: o[16x128] = W[16x96] @ P^T ; per warp, mma.sync fp16
            float accO[16][4];
            #pragma unroll
            for (int q = 0; q < 16; q++)
                #pragma unroll
                for (int v = 0; v < 4; v++) accO[q][v] = 0.f;
            uint32_t aAddr = WhB + (uint32_t)(wid * 16 + (lane & 7) + ((g & 1) << 3)) * 208u
                                 + (uint32_t)((g >> 1) << 4);
            uint32_t bAddr = PhB + (uint32_t)((lane & 7) + ((g >> 1) << 3)) * 208u
                                 + (uint32_t)((g & 1) << 4);
            #pragma unroll
            for (int k = 0; k < 6; k++) {
                uint32_t a0, a1, a2, a3;
                ldsm4(aAddr + (uint32_t)k * 32u, a0, a1, a2, a3);
                #pragma unroll
                for (int q = 0; q < 8; q++) {
                    uint32_t r0, r1, r2, r3;
                    ldsm4(bAddr + (uint32_t)(q * 16 * 208) + (uint32_t)k * 32u, r0, r1, r2, r3);
                    mma_f16(accO[2 * q],     a0, a1, a2, a3, r0, r1);
                    mma_f16(accO[2 * q + 1], a0, a1, a2, a3, r2, r3);
                }
            }
            // epilogue: + Pc + tokens, LN1, pack fp16 hi/lo, store
            int ra = wid * 16 + (lane >> 2);
            int rb = ra + 8;
            int iiA = ra % 24, iiB = rb % 24;
            float zA = zsm[ra], zB = zsm[rb];
            float sA0 = 0.f, sA1 = 0.f, sB0 = 0.f, sB1 = 0.f;
            #pragma unroll
            for (int t = 0; t < 16; t++) {
                int c = t * 8 + ((lane & 3) << 1);
                float pc0 = pcs[c], pc1 = pcs[c + 1];
                float y0 = accO[t][0] + pc0 + zA * fesm[iiA * 133 + c];
                float y1 = accO[t][1] + pc1 + zA * fesm[iiA * 133 + c + 1];
                float y2 = accO[t][2] + pc0 + zB * fesm[iiB * 133 + c];
                float y3 = accO[t][3] + pc1 + zB * fesm[iiB * 133 + c + 1];
                accO[t][0] = y0; accO[t][1] = y1; accO[t][2] = y2; accO[t][3] = y3;
                sA0 += y0 + y1; sA1 += y0 * y0 + y1 * y1;
                sB0 += y2 + y3; sB1 += y2 * y2 + y3 * y3;
            }
            #pragma unroll
            for (int m = 1; m < 4; m <<= 1) {
                sA0 += __shfl_xor_sync(0xffffffffu, sA0, m);
                sA1 += __shfl_xor_sync(0xffffffffu, sA1, m);
                sB0 += __shfl_xor_sync(0xffffffffu, sB0, m);
                sB1 += __shfl_xor_sync(0xffffffffu, sB1, m);
            }
            float mA = sA0 * (1.f / 128.f);
            float rA = rsqrtf(sA1 * (1.f / 128.f) - mA * mA + 1e-5f);
            float mB = sB0 * (1.f / 128.f);
            float rB = rsqrtf(sB1 * (1.f / 128.f) - mB * mB + 1e-5f);
            unsigned int* dstA = &g_t[br][(size_t)(blk * 96 + ra) * 128];
            unsigned int* dstB = &g_t[br][(size_t)(blk * 96 + rb) * 128];
            #pragma unroll
            for (int t = 0; t < 16; t++) {
                int c = t * 8 + ((lane & 3) << 1);
                float g0 = c1g[c], g1 = c1g[c + 1], b0 = c1b[c], b1 = c1b[c + 1];
                float tA0 = (accO[t][0] - mA) * rA * g0 + b0;
                float tA1 = (accO[t][1] - mA) * rA * g1 + b1;
                float tB0 = (accO[t][2] - mB) * rB * g0 + b0;
                float tB1 = (accO[t][3] - mB) * rB * g1 + b1;
                __half hA0 = __float2half_rn(tA0), hA1 = __float2half_rn(tA1);
                __half hB0 = __float2half_rn(tB0), hB1 = __float2half_rn(tB1);
                uint2 vA, vB;
                vA.x = pk2h(hA0, __float2half_rn(tA0 - __half2float(hA0)));
                vA.y = pk2h(hA1, __float2half_rn(tA1 - __half2float(hA1)));
                vB.x = pk2h(hB0, __float2half_rn(tB0 - __half2float(hB0)));
                vB.y = pk2h(hB1, __float2half_rn(tB1 - __half2float(hB1)));
                *(uint2*)&dstA[c] = vA;
                *(uint2*)&dstB[c] = vB;
            }
        }
        __syncthreads();
    }
}

// ------------------------- K3: FFN single-fp16 mma, exact residual ------------
#define TAH_OFF 0
#define TAL_OFF 69632
#define W1B_OFF 139264   /* 2 x 17408 */
#define W2B_OFF 174080   /* 2 x 18432 */
#define B1S_OFF 210944
#define GWS_OFF 212992
#define B2S_OFF 214016
#define OAC_OFF 214528
#define SM3 215040

__global__ __launch_bounds__(512, 1)
void ffn_mma(const float* __restrict__ b1g, const float* __restrict__ b2g,
             float* __restrict__ out) {
    extern __shared__ char smc[];
    uint32_t sb = cvta_s(smc);
    int tid = threadIdx.x, wid = tid >> 5, lane = tid & 31;
    int tile = blockIdx.x;
    int g = lane >> 3;
    int br = wid >> 3;
    int m0 = (wid & 7) * 16;

    float* b1s = (float*)(smc + B1S_OFF);
    float* gws = (float*)(smc + GWS_OFF);
    float* b2s = (float*)(smc + B2S_OFF);
    float* oac = (float*)(smc + OAC_OFF);
    if (tid < 512) b1s[tid] = b1g[tid];
    if (tid < 256) gws[tid] = ((const float*)g_gw)[tid];
    else if (tid < 384) b2s[tid - 256] = b2g[tid - 256];

    // stage t tile (both branches): unpack fp16 hi/lo into padded rows
    for (int b2 = 0; b2 < 2; b2++) {
        const uint2* src = (const uint2*)&g_t[b2][(size_t)tile * 16384];
        for (int idx = tid; idx < 8192; idx += 512) {
            uint2 v = src[idx];
            int r = idx >> 6, pr = idx & 63;
            uint32_t hi = (v.x & 0xFFFFu) | (v.y << 16);
            uint32_t lo = (v.x >> 16) | (v.y & 0xFFFF0000u);
            uint32_t boff = (uint32_t)(b2 * 128 + r) * 272u + (uint32_t)pr * 4u;
            *(uint32_t*)(smc + TAH_OFF + boff) = hi;
            *(uint32_t*)(smc + TAL_OFF + boff) = lo;
        }
    }

    // prefetch chunk 0
    {
        uint32_t w1d = sb + W1B_OFF;
        for (int i = tid; i < 1024; i += 512) {
            int row = i >> 4, col = i & 15;
            CPA16(w1d + row * 272 + col * 16, (const char*)&g_w1h[0][0] + row * 256 + col * 16);
        }
        uint32_t w2d = sb + W2B_OFF;
        for (int i = tid; i < 1024; i += 512) {
            int row = i >> 3, col = i & 7;
            CPA16(w2d + row * 144 + col * 16, (const char*)&g_w2h[0][0] + row * 1024 + col * 16);
        }
        CPA_COMMIT();
    }
    __syncthreads();

    uint32_t aRowOff = (uint32_t)((lane & 7) + ((g & 1) << 3));
    uint32_t aKOff   = (uint32_t)((g >> 1) << 4);
    uint32_t bPart272 = (uint32_t)(((lane & 7) + ((g >> 1) << 3)) * 272 + ((g & 1) << 4));
    uint32_t bPart144 = (uint32_t)(((lane & 7) + ((g >> 1) << 3)) * 144 + ((g & 1) << 4));
    uint32_t aBaseRow = (uint32_t)(br * 128 + m0) + aRowOff;

    float accF[16][4];
    #pragma unroll
    for (int q = 0; q < 16; q++)
        #pragma unroll
        for (int v = 0; v < 4; v++) accF[q][v] = 0.f;

    for (int ch = 0; ch < 8; ch++) {
        if (ch < 7) {
            int nc = ch + 1, nb = nc & 1;
            uint32_t w1d = sb + W1B_OFF + nb * 17408;
            const char* w1src = (const char*)&g_w1h[nc * 64][0];
            for (int i = tid; i < 1024; i += 512) {
                int row = i >> 4, col = i & 15;
                CPA16(w1d + row * 272 + col * 16, w1src + row * 256 + col * 16);
            }
            uint32_t w2d = sb + W2B_OFF + nb * 18432;
            const char* w2src = (const char*)&g_w2h[0][0] + nc * 128;
            for (int i = tid; i < 1024; i += 512) {
                int row = i >> 3, col = i & 7;
                CPA16(w2d + row * 144 + col * 16, w2src + row * 1024 + col * 16);
            }
            CPA_COMMIT();
            asm volatile("cp.async.wait_group 1;" ::: "memory");
        } else {
            asm volatile("cp.async.wait_group 0;" ::: "memory");
        }
        __syncthreads();

        int cb = ch & 1;
        // ---- GEMM1: h[16][64] = t_hi[16][128] @ W1ch^T (single fp16 pass) ----
        float acc1[8][4];
        #pragma unroll
        for (int q = 0; q < 8; q++)
            #pragma unroll
            for (int v = 0; v < 4; v++) acc1[q][v] = 0.f;
        uint32_t aHi = sb + TAH_OFF + aBaseRow * 272u + aKOff;
        uint32_t w1b = sb + W1B_OFF + cb * 17408 + bPart272;
        #pragma unroll
        for (int k = 0; k < 8; k++) {
            uint32_t h0, h1, h2, h3;
            ldsm4(aHi + (uint32_t)k * 32u, h0, h1, h2, h3);
            #pragma unroll
            for (int q = 0; q < 4; q++) {
                uint32_t r0, r1, r2, r3;
                ldsm4(w1b + (uint32_t)(q * 16 * 272) + (uint32_t)k * 32u, r0, r1, r2, r3);
                mma_f16(acc1[2 * q],     h0, h1, h2, h3, r0, r1);
                mma_f16(acc1[2 * q + 1], h0, h1, h2, h3, r2, r3);
            }
        }
        // ---- GEMM2: accF += relu(h+b1)[16][64] @ W2ch^T (single fp16) ----
        uint32_t w2b = sb + W2B_OFF + cb * 18432 + bPart144;
        #pragma unroll
        for (int ks = 0; ks < 4; ks++) {
            uint32_t ah0, ah1, ah2, ah3;
            {
                int t0i = 2 * ks, t1i = 2 * ks + 1;
                int cc0 = ch * 64 + t0i * 8 + ((lane & 3) << 1);
                int cc1 = ch * 64 + t1i * 8 + ((lane & 3) << 1);
                float b00 = b1s[cc0], b01 = b1s[cc0 + 1];
                float b10 = b1s[cc1], b11 = b1s[cc1 + 1];
                float v0 = fmaxf(acc1[t0i][0] + b00, 0.f);
                float v1 = fmaxf(acc1[t0i][1] + b01, 0.f);
                float v2 = fmaxf(acc1[t0i][2] + b00, 0.f);
                float v3 = fmaxf(acc1[t0i][3] + b01, 0.f);
                float w0 = fmaxf(acc1[t1i][0] + b10, 0.f);
                float w1 = fmaxf(acc1[t1i][1] + b11, 0.f);
                float w2 = fmaxf(acc1[t1i][2] + b10, 0.f);
                float w3 = fmaxf(acc1[t1i][3] + b11, 0.f);
                ah0 = pk2h(__float2half_rn(v0), __float2half_rn(v1));
                ah1 = pk2h(__float2half_rn(v2), __float2half_rn(v3));
                ah2 = pk2h(__float2half_rn(w0), __float2half_rn(w1));
                ah3 = pk2h(__float2half_rn(w2), __float2half_rn(w3));
            }
            #pragma unroll
            for (int q = 0; q < 8; q++) {
                uint32_t r0, r1, r2, r3;
                ldsm4(w2b + (uint32_t)(q * 16 * 144) + (uint32_t)ks * 32u, r0, r1, r2, r3);
                mma_f16(accF[2 * q],     ah0, ah1, ah2, ah3, r0, r1);
                mma_f16(accF[2 * q + 1], ah0, ah1, ah2, ah3, r2, r3);
            }
        }
        __syncthreads();
    }

    // ---- epilogue: exact residual (hi+lo) + fused LN2 + head ----
    float sA0 = 0.f, sA1 = 0.f, sA2 = 0.f, sB0 = 0.f, sB1 = 0.f, sB2 = 0.f;
    int ra = br * 128 + m0 + (lane >> 2);
    #pragma unroll
    for (int t = 0; t < 16; t++) {
        int c = t * 8 + ((lane & 3) << 1);
        uint32_t hia = *(const uint32_t*)(smc + TAH_OFF + ra * 272 + c * 2);
        uint32_t loa = *(const uint32_t*)(smc + TAL_OFF + ra * 272 + c * 2);
        uint32_t hib = *(const uint32_t*)(smc + TAH_OFF + (ra + 8) * 272 + c * 2);
        uint32_t lob = *(const uint32_t*)(smc + TAL_OFF + (ra + 8) * 272 + c * 2);
        float t0a = hLO(hia) + hLO(loa), t1a = hHI(hia) + hHI(loa);
        float t0b = hLO(hib) + hLO(lob), t1b = hHI(hib) + hHI(lob);
        float bz0 = b2s[c], bz1 = b2s[c + 1];
        float g0 = gws[br * 128 + c], g1 = gws[br * 128 + c + 1];
        float y0 = accF[t][0] + t0a + bz0;
        float y1 = accF[t][1] + t1a + bz1;
        float y2 = accF[t][2] + t0b + bz0;
        float y3 = accF[t][3] + t1b + bz1;
        sA0 += y0 + y1; sA1 += y0 * y0 + y1 * y1; sA2 += y0 * g0 + y1 * g1;
        sB0 += y2 + y3; sB1 += y2 * y2 + y3 * y3; sB2 += y2 * g0 + y3 * g1;
    }
    #pragma unroll
    for (int m = 1; m < 4; m <<= 1) {
        sA0 += __shfl_xor_sync(0xffffffffu, sA0, m);
        sA1 += __shfl_xor_sync(0xffffffffu, sA1, m);
        sA2 += __shfl_xor_sync(0xffffffffu, sA2, m);
        sB0 += __shfl_xor_sync(0xffffffffu, sB0, m);
        sB1 += __shfl_xor_sync(0xffffffffu, sB1, m);
        sB2 += __shfl_xor_sync(0xffffffffu, sB2, m);
    }
    float sgw = g_sc[br][0], cst = g_sc[br][1];
    float mean = sA0 * (1.f / 128.f);
    float var = sA1 * (1.f / 128.f) - mean * mean;
    float resA = (sA2 - mean * sgw) * rsqrtf(var + 1e-5f) + cst;
    float meanb = sB0 * (1.f / 128.f);
    float varb = sB1 * (1.f / 128.f) - meanb * meanb;
    float resB = (sB2 - meanb * sgw) * rsqrtf(varb + 1e-5f) + cst;

    if (br == 0 && (lane & 3) == 0) {
        oac[m0 + (lane >> 2)] = resA;
        oac[m0 + 8 + (lane >> 2)] = resB;
    }
    __syncthreads();
    if (br == 1 && (lane & 3) == 0) {
        out[(size_t)tile * 128 + m0 + (lane >> 2)] = oac[m0 + (lane >> 2)] + resA;
        out[(size_t)tile * 128 + m0 + 8 + (lane >> 2)] = oac[m0 + 8 + (lane >> 2)] + resB;
    }
}

// ------------------------- launch -------------------------
extern "C" void kernel_launch(void* const* d_in, const int* in_sizes, int n_in,
                              void* d_out, int out_size) {
    const float* z    = (const float*)d_in[0];
    const float* fe   = (const float*)d_in[1];
    const float* inwp = (const float*)d_in[2];
    const float* inbp = (const float*)d_in[3];
    const float* outwp= (const float*)d_in[4];
    const float* outbp= (const float*)d_in[5];
    const float* inwf = (const float*)d_in[6];
    const float* inbf = (const float*)d_in[7];
    const float* outwf= (const float*)d_in[8];
    const float* outbf= (const float*)d_in[9];
    const float* ln1g = (const float*)d_in[10];
    const float* ln1b = (const float*)d_in[11];
    const float* w1   = (const float*)d_in[12];
    const float* b1   = (const float*)d_in[13];
    const float* w2   = (const float*)d_in[14];
    const float* b2   = (const float*)d_in[15];
    const float* ln2g = (const float*)d_in[16];
    const float* ln2b = (const float*)d_in[17];
    const float* oppw = (const float*)d_in[18];
    const float* oppb = (const float*)d_in[19];
    const float* opfw = (const float*)d_in[20];
    const float* opfb = (const float*)d_in[21];
    const float* alog = (const float*)d_in[22];
    const float* bp   = (const float*)d_in[23];
    const float* bf   = (const float*)d_in[24];

    int B = in_sizes[0] / Hx;
    int tiles = (B * Hx) / 128;
    cudaFuncSetAttribute(attn_k, cudaFuncAttributeMaxDynamicSharedMemorySize, K2BYTES);
    cudaFuncSetAttribute(ffn_mma, cudaFuncAttributeMaxDynamicSharedMemorySize, SM3);

    pre_qkv<<<dim3(6, 8), 256>>>(fe, inwp, inwf);
    pre_misc<<<dim3(2, 8), 256>>>(inbp, inbf, outwp, outbp, outwf, outbf,
                                  ln2g, ln2b, oppw, oppb, opfw, opfb, alog, bp, bf);
    pre_wimg<<<256, 256>>>(w1, w2);
    attn_k<<<B / 4, 256, K2BYTES>>>(z, fe, ln1g, ln1b);
    ffn_mma<<<tiles, 512, SM3>>>(b1, b2, (float*)d_out);
}

// round 10
// speedup vs baseline: 6.9400x; 1.0961x over previous
#include <cuda_runtime.h>
#include <cuda_fp16.h>
#include <math.h>
#include <stdint.h>

#define Hx 24
#define Dx 128
#define NHx 4
#define DHx 32
#define RS32 0.17677669529663687f

// ------------------------- device globals -------------------------
__device__ float g_E[2][3][Hx][Dx];
__device__ float g_Gt[2][Hx][NHx*Hx];    // transposed: [br][j][n*24+i]
__device__ float g_Mkt[2][Hx][NHx*Hx];   // transposed mask bias
__device__ float g_gq[2][NHx][Hx];
__device__ float g_gk[2][NHx][Hx];
__device__ __align__(16) __half g_Ph[2][Dx][104];   // fp16 P transposed [c][k], padded
__device__ float g_Pc[2][Dx];
__device__ float g_gw[2][Dx];
__device__ float g_sc[2][2];
__device__ unsigned int g_t[2][25165824u];   // packed fp16 hi | lo<<16
__device__ __half g_w1h[512][128];
__device__ __half g_w2h[128][512];

// ------------------------- helpers -------------------------
__device__ __forceinline__ uint32_t cvta_s(const void* p) {
    uint32_t a;
    asm("{ .reg .u64 t; cvta.to.shared.u64 t, %1; cvt.u32.u64 %0, t; }" : "=r"(a) : "l"(p));
    return a;
}
__device__ __forceinline__ void ldsm4(uint32_t addr, uint32_t& r0, uint32_t& r1,
                                      uint32_t& r2, uint32_t& r3) {
    asm volatile("ldmatrix.sync.aligned.m8n8.x4.shared.b16 {%0,%1,%2,%3}, [%4];"
                 : "=r"(r0), "=r"(r1), "=r"(r2), "=r"(r3) : "r"(addr));
}
__device__ __forceinline__ void mma_f16(float d[4], uint32_t a0, uint32_t a1, uint32_t a2,
                                        uint32_t a3, uint32_t b0, uint32_t b1) {
    asm volatile("mma.sync.aligned.m16n8k16.row.col.f32.f16.f16.f32 "
                 "{%0,%1,%2,%3}, {%4,%5,%6,%7}, {%8,%9}, {%0,%1,%2,%3};"
                 : "+f"(d[0]), "+f"(d[1]), "+f"(d[2]), "+f"(d[3])
                 : "r"(a0), "r"(a1), "r"(a2), "r"(a3), "r"(b0), "r"(b1));
}
__device__ __forceinline__ uint32_t pk2h(__half e0, __half e1) {
    return (uint32_t)__half_as_ushort(e0) | ((uint32_t)__half_as_ushort(e1) << 16);
}
__device__ __forceinline__ float hLO(uint32_t v) {
    return __half2float(__ushort_as_half((unsigned short)(v & 0xFFFFu)));
}
__device__ __forceinline__ float hHI(uint32_t v) {
    return __half2float(__ushort_as_half((unsigned short)(v >> 16)));
}
#define CPA16(d, s) asm volatile("cp.async.cg.shared.global [%0], [%1], 16;" :: "r"(d), "l"(s))
#define CPA_COMMIT() asm volatile("cp.async.commit_group;" ::: "memory")

// ------------------------- precompute 1 -------------------------
__global__ void pre_qkv(const float* __restrict__ fe, const float* __restrict__ inwp,
                        const float* __restrict__ inwf) {
    int br = blockIdx.x / 3, which = blockIdx.x % 3;
    const float* W = (br ? inwf : inwp) + which * Dx * Dx;
    __shared__ float fes[Hx * Dx];
    for (int idx = threadIdx.x; idx < Hx * Dx; idx += 256) fes[idx] = fe[idx];
    __syncthreads();
    for (int idx = blockIdx.y * 256 + threadIdx.x; idx < Hx * Dx; idx += 2048) {
        int i = idx >> 7, c = idx & 127;
        float s = 0.f;
        #pragma unroll 8
        for (int d = 0; d < Dx; d++) s += fes[i * Dx + d] * W[c * Dx + d];
        g_E[br][which][i][c] = s;
    }
}

// ------------------------- precompute 2 -------------------------
__global__ void pre_misc(const float* __restrict__ inbp, const float* __restrict__ inbf,
                         const float* __restrict__ outwp, const float* __restrict__ outbp,
                         const float* __restrict__ outwf, const float* __restrict__ outbf,
                         const float* __restrict__ ln2g, const float* __restrict__ ln2b,
                         const float* __restrict__ oppw, const float* __restrict__ oppb,
                         const float* __restrict__ opfw, const float* __restrict__ opfb,
                         const float* __restrict__ alog,
                         const float* __restrict__ biasp, const float* __restrict__ biasf) {
    int br = blockIdx.x, gy = blockIdx.y;
    const float* inb  = br ? inbf  : inbp;
    const float* outw = br ? outwf : outwp;
    const float* outb = br ? outbf : outbp;
    const float* opw  = br ? opfw  : oppw;
    const float* opb  = br ? opfb  : oppb;
    const float* bias = br ? biasf : biasp;
    const float* qb = inb, *kb = inb + Dx, *vb = inb + 2 * Dx;
    __shared__ float g0s[NHx];
    int tid = threadIdx.x;
    if (tid < NHx) {
        float s = 0.f;
        for (int d = 0; d < DHx; d++) s += qb[tid * DHx + d] * kb[tid * DHx + d];
        g0s[tid] = s * RS32;
    }
    __syncthreads();
    int base = gy * 256 + tid;
    for (int idx = base; idx < NHx * Hx; idx += 2048) {
        int n = idx / Hx, i = idx % Hx;
        float s1 = 0.f, s2 = 0.f;
        for (int d = 0; d < DHx; d++) {
            s1 += g_E[br][0][i][n * DHx + d] * kb[n * DHx + d];
            s2 += g_E[br][1][i][n * DHx + d] * qb[n * DHx + d];
        }
        g_gq[br][n][i] = s1 * RS32;
        g_gk[br][n][i] = s2 * RS32;
    }
    for (int idx = base; idx < NHx * Hx * Hx; idx += 2048) {
        int n = idx / (Hx * Hx), i = (idx / Hx) % Hx, j = idx % Hx;
        float s = 0.f;
        for (int d = 0; d < DHx; d++)
            s += g_E[br][0][i][n * DHx + d] * g_E[br][1][j][n * DHx + d];
        g_Gt[br][j][n * Hx + i] = s * RS32;
        bool valid = (br == 0) ? (j <= i) : (j >= i);
        g_Mkt[br][j][n * Hx + i] = valid ? bias[j - i + Hx - 1] + g0s[n] : -1e30f;
    }
    for (int idx = base; idx < NHx * Hx * Dx; idx += 2048) {
        int k = idx >> 7, c = idx & 127;
        int n = k / Hx, j = k % Hx;
        float s = 0.f;
        for (int d = 0; d < DHx; d++)
            s += outw[c * Dx + n * DHx + d] * g_E[br][2][j][n * DHx + d];
        g_Ph[br][c][k] = __float2half_rn(s);
    }
    if (gy == 0) {
        float e0 = expf(alog[0]), e1 = expf(alog[1]);
        float alpha = (br == 0 ? e0 : e1) / (e0 + e1);
        for (int idx = tid; idx < Dx; idx += 256) {
            float s = outb[idx];
            for (int m = 0; m < Dx; m++) s += outw[idx * Dx + m] * vb[m];
            g_Pc[br][idx] = s;
            g_gw[br][idx] = ln2g[idx] * opw[idx] * alpha;
        }
        __syncthreads();
        __threadfence();
        if (tid == 0) {
            float sgw = 0.f, cst = 0.f;
            for (int c = 0; c < Dx; c++) { sgw += g_gw[br][c]; cst += ln2b[c] * opw[c]; }
            g_sc[br][0] = sgw;
            g_sc[br][1] = alpha * (cst + opb[0]);
        }
    }
}

// ------------------------- precompute 3: fp16 weight images -------------------------
__global__ void pre_wimg(const float* __restrict__ w1, const float* __restrict__ w2) {
    int idx = blockIdx.x * 256 + threadIdx.x;
    if (idx >= 65536) return;
    {
        int f = idx >> 7, c = idx & 127;
        g_w1h[f][c] = __float2half_rn(w1[idx]);
    }
    {
        int n = idx >> 9, ff = idx & 511;
        g_w2h[n][ff] = __float2half_rn(w2[idx]);
    }
}

// ------------------------- K2: attention (mma.sync) + LN1 -> packed fp16 t ----------
#define FE0 480
#define WH0 3672
#define PH0 8664
#define K2BYTES 61280

__global__ __launch_bounds__(256)
void attn_k(const float* __restrict__ z, const float* __restrict__ fe,
            const float* __restrict__ ln1g, const float* __restrict__ ln1b) {
    extern __shared__ float sm[];
    float* zsm  = sm;
    float* c1g  = sm + 96;
    float* c1b  = sm + 224;
    float* pcs  = sm + 352;
    float* fesm = sm + FE0;
    __half* Wh  = (__half*)(sm + WH0);
    uint32_t sb = cvta_s(sm);
    uint32_t WhB = sb + WH0 * 4;
    uint32_t PhB = sb + PH0 * 4;
    int tid = threadIdx.x, wid = tid >> 5, lane = tid & 31;
    int g = lane >> 3;
    int blk = blockIdx.x;

    if (tid < 96) zsm[tid] = z[blk * 96 + tid];
    if (tid >= 128) { c1g[tid - 128] = ln1g[tid - 128]; c1b[tid - 128] = ln1b[tid - 128]; }
    for (int idx = tid; idx < Hx * Dx; idx += 256)
        fesm[(idx >> 7) * 133 + (idx & 127)] = fe[idx];
    __syncthreads();

    for (int br = 0; br < 2; br++) {
        // stage Ph + Pc
        {
            const uint4* ps = (const uint4*)&g_Ph[br][0][0];
            uint4* pd = (uint4*)(sm + PH0);
            for (int i = tid; i < 1664; i += 256) pd[i] = ps[i];
            if (tid < 128) pcs[tid] = g_Pc[br][tid];
        }
        // softmax + weight fold -> fp16 W  (coalesced transposed table reads)
        for (int rs = tid; rs < 384; rs += 256) {
            int bb = rs / 96, rem = rs % 96, n = rem / 24, i = rem % 24;
            int x = n * Hx + i;
            float zi = zsm[bb * 24 + i];
            const float* Gt = &g_Gt[br][0][x];    // stride NHx*Hx = 96 per j
            const float* Mt = &g_Mkt[br][0][x];
            const float* gkp = &g_gk[br][n][0];
            float gq = g_gq[br][n][i];
            float s[24]; float mx = -1e30f;
            #pragma unroll
            for (int j = 0; j < 24; j++) {
                float zj = zsm[bb * 24 + j];
                float v = zi * zj * Gt[j * 96] + zi * gq + zj * gkp[j] + Mt[j * 96];
                s[j] = v; mx = fmaxf(mx, v);
            }
            float sum = 0.f;
            #pragma unroll
            for (int j = 0; j < 24; j++) { s[j] = __expf(fmaxf(s[j] - mx, -80.f)); sum += s[j]; }
            float inv = 1.f / sum;
            __half* wrow = &Wh[(bb * 24 + i) * 104 + n * 24];
            #pragma unroll
            for (int j = 0; j < 24; j += 2) {
                *(uint32_t*)&wrow[j] = pk2h(__float2half_rn(s[j] * inv * zsm[bb * 24 + j]),
                                            __float2half_rn(s[j + 1] * inv * zsm[bb * 24 + j + 1]));
            }
        }
        __syncthreads();

        if (wid < 6) {
            // GEMM: o[16x128] = W[16x96] @ P^T ; per warp, mma.sync fp16
            float accO[16][4];
            #pragma unroll
            for (int q = 0; q < 16; q++)
                #pragma unroll
                for (int v = 0; v < 4; v++) accO[q][v] = 0.f;
            uint32_t aAddr = WhB + (uint32_t)(wid * 16 + (lane & 7) + ((g & 1) << 3)) * 208u
                                 + (uint32_t)((g >> 1) << 4);
            uint32_t bAddr = PhB + (uint32_t)((lane & 7) + ((g >> 1) << 3)) * 208u
                                 + (uint32_t)((g & 1) << 4);
            #pragma unroll
            for (int k = 0; k < 6; k++) {
                uint32_t a0, a1, a2, a3;
                ldsm4(aAddr + (uint32_t)k * 32u, a0, a1, a2, a3);
                #pragma unroll
                for (int q = 0; q < 8; q++) {
                    uint32_t r0, r1, r2, r3;
                    ldsm4(bAddr + (uint32_t)(q * 16 * 208) + (uint32_t)k * 32u, r0, r1, r2, r3);
                    mma_f16(accO[2 * q],     a0, a1, a2, a3, r0, r1);
                    mma_f16(accO[2 * q + 1], a0, a1, a2, a3, r2, r3);
                }
            }
            // epilogue: + Pc + tokens, LN1, pack fp16 hi/lo, store
            int ra = wid * 16 + (lane >> 2);
            int rb = ra + 8;
            int iiA = ra % 24, iiB = rb % 24;
            float zA = zsm[ra], zB = zsm[rb];
            float sA0 = 0.f, sA1 = 0.f, sB0 = 0.f, sB1 = 0.f;
            #pragma unroll
            for (int t = 0; t < 16; t++) {
                int c = t * 8 + ((lane & 3) << 1);
                float pc0 = pcs[c], pc1 = pcs[c + 1];
                float y0 = accO[t][0] + pc0 + zA * fesm[iiA * 133 + c];
                float y1 = accO[t][1] + pc1 + zA * fesm[iiA * 133 + c + 1];
                float y2 = accO[t][2] + pc0 + zB * fesm[iiB * 133 + c];
                float y3 = accO[t][3] + pc1 + zB * fesm[iiB * 133 + c + 1];
                accO[t][0] = y0; accO[t][1] = y1; accO[t][2] = y2; accO[t][3] = y3;
                sA0 += y0 + y1; sA1 += y0 * y0 + y1 * y1;
                sB0 += y2 + y3; sB1 += y2 * y2 + y3 * y3;
            }
            #pragma unroll
            for (int m = 1; m < 4; m <<= 1) {
                sA0 += __shfl_xor_sync(0xffffffffu, sA0, m);
                sA1 += __shfl_xor_sync(0xffffffffu, sA1, m);
                sB0 += __shfl_xor_sync(0xffffffffu, sB0, m);
                sB1 += __shfl_xor_sync(0xffffffffu, sB1, m);
            }
            float mA = sA0 * (1.f / 128.f);
            float rA = rsqrtf(sA1 * (1.f / 128.f) - mA * mA + 1e-5f);
            float mB = sB0 * (1.f / 128.f);
            float rB = rsqrtf(sB1 * (1.f / 128.f) - mB * mB + 1e-5f);
            unsigned int* dstA = &g_t[br][(size_t)(blk * 96 + ra) * 128];
            unsigned int* dstB = &g_t[br][(size_t)(blk * 96 + rb) * 128];
            #pragma unroll
            for (int t = 0; t < 16; t++) {
                int c = t * 8 + ((lane & 3) << 1);
                float g0 = c1g[c], g1 = c1g[c + 1], b0 = c1b[c], b1 = c1b[c + 1];
                float tA0 = (accO[t][0] - mA) * rA * g0 + b0;
                float tA1 = (accO[t][1] - mA) * rA * g1 + b1;
                float tB0 = (accO[t][2] - mB) * rB * g0 + b0;
                float tB1 = (accO[t][3] - mB) * rB * g1 + b1;
                __half hA0 = __float2half_rn(tA0), hA1 = __float2half_rn(tA1);
                __half hB0 = __float2half_rn(tB0), hB1 = __float2half_rn(tB1);
                uint2 vA, vB;
                vA.x = pk2h(hA0, __float2half_rn(tA0 - __half2float(hA0)));
                vA.y = pk2h(hA1, __float2half_rn(tA1 - __half2float(hA1)));
                vB.x = pk2h(hB0, __float2half_rn(tB0 - __half2float(hB0)));
                vB.y = pk2h(hB1, __float2half_rn(tB1 - __half2float(hB1)));
                *(uint2*)&dstA[c] = vA;
                *(uint2*)&dstB[c] = vB;
            }
        }
        __syncthreads();
    }
}

// ------------------------- K3: FFN single-fp16 mma, exact residual ------------
#define TAH_OFF 0
#define TAL_OFF 69632
#define W1B_OFF 139264   /* 2 x 17408 */
#define W2B_OFF 174080   /* 2 x 18432 */
#define B1S_OFF 210944
#define GWS_OFF 212992
#define B2S_OFF 214016
#define OAC_OFF 214528
#define SM3 215040

__global__ __launch_bounds__(512, 1)
void ffn_mma(const float* __restrict__ b1g, const float* __restrict__ b2g,
             float* __restrict__ out) {
    extern __shared__ char smc[];
    uint32_t sb = cvta_s(smc);
    int tid = threadIdx.x, wid = tid >> 5, lane = tid & 31;
    int tile = blockIdx.x;
    int g = lane >> 3;
    int br = wid >> 3;
    int m0 = (wid & 7) * 16;

    float* b1s = (float*)(smc + B1S_OFF);
    float* gws = (float*)(smc + GWS_OFF);
    float* b2s = (float*)(smc + B2S_OFF);
    float* oac = (float*)(smc + OAC_OFF);
    if (tid < 512) b1s[tid] = b1g[tid];
    if (tid < 256) gws[tid] = ((const float*)g_gw)[tid];
    else if (tid < 384) b2s[tid - 256] = b2g[tid - 256];

    // stage t tile (both branches): unpack fp16 hi/lo into padded rows
    for (int b2 = 0; b2 < 2; b2++) {
        const uint2* src = (const uint2*)&g_t[b2][(size_t)tile * 16384];
        for (int idx = tid; idx < 8192; idx += 512) {
            uint2 v = src[idx];
            int r = idx >> 6, pr = idx & 63;
            uint32_t hi = (v.x & 0xFFFFu) | (v.y << 16);
            uint32_t lo = (v.x >> 16) | (v.y & 0xFFFF0000u);
            uint32_t boff = (uint32_t)(b2 * 128 + r) * 272u + (uint32_t)pr * 4u;
            *(uint32_t*)(smc + TAH_OFF + boff) = hi;
            *(uint32_t*)(smc + TAL_OFF + boff) = lo;
        }
    }

    // prefetch chunk 0
    {
        uint32_t w1d = sb + W1B_OFF;
        for (int i = tid; i < 1024; i += 512) {
            int row = i >> 4, col = i & 15;
            CPA16(w1d + row * 272 + col * 16, (const char*)&g_w1h[0][0] + row * 256 + col * 16);
        }
        uint32_t w2d = sb + W2B_OFF;
        for (int i = tid; i < 1024; i += 512) {
            int row = i >> 3, col = i & 7;
            CPA16(w2d + row * 144 + col * 16, (const char*)&g_w2h[0][0] + row * 1024 + col * 16);
        }
        CPA_COMMIT();
    }
    __syncthreads();

    uint32_t aRowOff = (uint32_t)((lane & 7) + ((g & 1) << 3));
    uint32_t aKOff   = (uint32_t)((g >> 1) << 4);
    uint32_t bPart272 = (uint32_t)(((lane & 7) + ((g >> 1) << 3)) * 272 + ((g & 1) << 4));
    uint32_t bPart144 = (uint32_t)(((lane & 7) + ((g >> 1) << 3)) * 144 + ((g & 1) << 4));
    uint32_t aBaseRow = (uint32_t)(br * 128 + m0) + aRowOff;

    float accF[16][4];
    #pragma unroll
    for (int q = 0; q < 16; q++)
        #pragma unroll
        for (int v = 0; v < 4; v++) accF[q][v] = 0.f;

    for (int ch = 0; ch < 8; ch++) {
        if (ch < 7) {
            int nc = ch + 1, nb = nc & 1;
            uint32_t w1d = sb + W1B_OFF + nb * 17408;
            const char* w1src = (const char*)&g_w1h[nc * 64][0];
            for (int i = tid; i < 1024; i += 512) {
                int row = i >> 4, col = i & 15;
                CPA16(w1d + row * 272 + col * 16, w1src + row * 256 + col * 16);
            }
            uint32_t w2d = sb + W2B_OFF + nb * 18432;
            const char* w2src = (const char*)&g_w2h[0][0] + nc * 128;
            for (int i = tid; i < 1024; i += 512) {
                int row = i >> 3, col = i & 7;
                CPA16(w2d + row * 144 + col * 16, w2src + row * 1024 + col * 16);
            }
            CPA_COMMIT();
            asm volatile("cp.async.wait_group 1;" ::: "memory");
        } else {
            asm volatile("cp.async.wait_group 0;" ::: "memory");
        }
        __syncthreads();

        int cb = ch & 1;
        // ---- GEMM1: h[16][64] = t_hi[16][128] @ W1ch^T (single fp16 pass) ----
        float acc1[8][4];
        #pragma unroll
        for (int q = 0; q < 8; q++)
            #pragma unroll
            for (int v = 0; v < 4; v++) acc1[q][v] = 0.f;
        uint32_t aHi = sb + TAH_OFF + aBaseRow * 272u + aKOff;
        uint32_t w1b = sb + W1B_OFF + cb * 17408 + bPart272;
        #pragma unroll
        for (int k = 0; k < 8; k++) {
            uint32_t h0, h1, h2, h3;
            ldsm4(aHi + (uint32_t)k * 32u, h0, h1, h2, h3);
            #pragma unroll
            for (int q = 0; q < 4; q++) {
                uint32_t r0, r1, r2, r3;
                ldsm4(w1b + (uint32_t)(q * 16 * 272) + (uint32_t)k * 32u, r0, r1, r2, r3);
                mma_f16(acc1[2 * q],     h0, h1, h2, h3, r0, r1);
                mma_f16(acc1[2 * q + 1], h0, h1, h2, h3, r2, r3);
            }
        }
        // ---- GEMM2: accF += relu(h+b1)[16][64] @ W2ch^T (single fp16) ----
        uint32_t w2b = sb + W2B_OFF + cb * 18432 + bPart144;
        #pragma unroll
        for (int ks = 0; ks < 4; ks++) {
            uint32_t ah0, ah1, ah2, ah3;
            {
                int t0i = 2 * ks, t1i = 2 * ks + 1;
                int cc0 = ch * 64 + t0i * 8 + ((lane & 3) << 1);
                int cc1 = ch * 64 + t1i * 8 + ((lane & 3) << 1);
                float b00 = b1s[cc0], b01 = b1s[cc0 + 1];
                float b10 = b1s[cc1], b11 = b1s[cc1 + 1];
                float v0 = fmaxf(acc1[t0i][0] + b00, 0.f);
                float v1 = fmaxf(acc1[t0i][1] + b01, 0.f);
                float v2 = fmaxf(acc1[t0i][2] + b00, 0.f);
                float v3 = fmaxf(acc1[t0i][3] + b01, 0.f);
                float w0 = fmaxf(acc1[t1i][0] + b10, 0.f);
                float w1 = fmaxf(acc1[t1i][1] + b11, 0.f);
                float w2 = fmaxf(acc1[t1i][2] + b10, 0.f);
                float w3 = fmaxf(acc1[t1i][3] + b11, 0.f);
                ah0 = pk2h(__float2half_rn(v0), __float2half_rn(v1));
                ah1 = pk2h(__float2half_rn(v2), __float2half_rn(v3));
                ah2 = pk2h(__float2half_rn(w0), __float2half_rn(w1));
                ah3 = pk2h(__float2half_rn(w2), __float2half_rn(w3));
            }
            #pragma unroll
            for (int q = 0; q < 8; q++) {
                uint32_t r0, r1, r2, r3;
                ldsm4(w2b + (uint32_t)(q * 16 * 144) + (uint32_t)ks * 32u, r0, r1, r2, r3);
                mma_f16(accF[2 * q],     ah0, ah1, ah2, ah3, r0, r1);
                mma_f16(accF[2 * q + 1], ah0, ah1, ah2, ah3, r2, r3);
            }
        }
        __syncthreads();
    }

    // ---- epilogue: exact residual (hi+lo) + fused LN2 + head ----
    float sA0 = 0.f, sA1 = 0.f, sA2 = 0.f, sB0 = 0.f, sB1 = 0.f, sB2 = 0.f;
    int ra = br * 128 + m0 + (lane >> 2);
    #pragma unroll
    for (int t = 0; t < 16; t++) {
        int c = t * 8 + ((lane & 3) << 1);
        uint32_t hia = *(const uint32_t*)(smc + TAH_OFF + ra * 272 + c * 2);
        uint32_t loa = *(const uint32_t*)(smc + TAL_OFF + ra * 272 + c * 2);
        uint32_t hib = *(const uint32_t*)(smc + TAH_OFF + (ra + 8) * 272 + c * 2);
        uint32_t lob = *(const uint32_t*)(smc + TAL_OFF + (ra + 8) * 272 + c * 2);
        float t0a = hLO(hia) + hLO(loa), t1a = hHI(hia) + hHI(loa);
        float t0b = hLO(hib) + hLO(lob), t1b = hHI(hib) + hHI(lob);
        float bz0 = b2s[c], bz1 = b2s[c + 1];
        float g0 = gws[br * 128 + c], g1 = gws[br * 128 + c + 1];
        float y0 = accF[t][0] + t0a + bz0;
        float y1 = accF[t][1] + t1a + bz1;
        float y2 = accF[t][2] + t0b + bz0;
        float y3 = accF[t][3] + t1b + bz1;
        sA0 += y0 + y1; sA1 += y0 * y0 + y1 * y1; sA2 += y0 * g0 + y1 * g1;
        sB0 += y2 + y3; sB1 += y2 * y2 + y3 * y3; sB2 += y2 * g0 + y3 * g1;
    }
    #pragma unroll
    for (int m = 1; m < 4; m <<= 1) {
        sA0 += __shfl_xor_sync(0xffffffffu, sA0, m);
        sA1 += __shfl_xor_sync(0xffffffffu, sA1, m);
        sA2 += __shfl_xor_sync(0xffffffffu, sA2, m);
        sB0 += __shfl_xor_sync(0xffffffffu, sB0, m);
        sB1 += __shfl_xor_sync(0xffffffffu, sB1, m);
        sB2 += __shfl_xor_sync(0xffffffffu, sB2, m);
    }
    float sgw = g_sc[br][0], cst = g_sc[br][1];
    float mean = sA0 * (1.f / 128.f);
    float var = sA1 * (1.f / 128.f) - mean * mean;
    float resA = (sA2 - mean * sgw) * rsqrtf(var + 1e-5f) + cst;
    float meanb = sB0 * (1.f / 128.f);
    float varb = sB1 * (1.f / 128.f) - meanb * meanb;
    float resB = (sB2 - meanb * sgw) * rsqrtf(varb + 1e-5f) + cst;

    if (br == 0 && (lane & 3) == 0) {
        oac[m0 + (lane >> 2)] = resA;
        oac[m0 + 8 + (lane >> 2)] = resB;
    }
    __syncthreads();
    if (br == 1 && (lane & 3) == 0) {
        out[(size_t)tile * 128 + m0 + (lane >> 2)] = oac[m0 + (lane >> 2)] + resA;
        out[(size_t)tile * 128 + m0 + 8 + (lane >> 2)] = oac[m0 + 8 + (lane >> 2)] + resB;
    }
}

// ------------------------- launch -------------------------
extern "C" void kernel_launch(void* const* d_in, const int* in_sizes, int n_in,
                              void* d_out, int out_size) {
    const float* z    = (const float*)d_in[0];
    const float* fe   = (const float*)d_in[1];
    const float* inwp = (const float*)d_in[2];
    const float* inbp = (const float*)d_in[3];
    const float* outwp= (const float*)d_in[4];
    const float* outbp= (const float*)d_in[5];
    const float* inwf = (const float*)d_in[6];
    const float* inbf = (const float*)d_in[7];
    const float* outwf= (const float*)d_in[8];
    const float* outbf= (const float*)d_in[9];
    const float* ln1g = (const float*)d_in[10];
    const float* ln1b = (const float*)d_in[11];
    const float* w1   = (const float*)d_in[12];
    const float* b1   = (const float*)d_in[13];
    const float* w2   = (const float*)d_in[14];
    const float* b2   = (const float*)d_in[15];
    const float* ln2g = (const float*)d_in[16];
    const float* ln2b = (const float*)d_in[17];
    const float* oppw = (const float*)d_in[18];
    const float* oppb = (const float*)d_in[19];
    const float* opfw = (const float*)d_in[20];
    const float* opfb = (const float*)d_in[21];
    const float* alog = (const float*)d_in[22];
    const float* bp   = (const float*)d_in[23];
    const float* bf   = (const float*)d_in[24];

    int B = in_sizes[0] / Hx;
    int tiles = (B * Hx) / 128;
    cudaFuncSetAttribute(attn_k, cudaFuncAttributeMaxDynamicSharedMemorySize, K2BYTES);
    cudaFuncSetAttribute(ffn_mma, cudaFuncAttributeMaxDynamicSharedMemorySize, SM3);

    pre_qkv<<<dim3(6, 8), 256>>>(fe, inwp, inwf);
    pre_misc<<<dim3(2, 8), 256>>>(inbp, inbf, outwp, outbp, outwf, outbf,
                                  ln2g, ln2b, oppw, oppb, opfw, opfb, alog, bp, bf);
    pre_wimg<<<256, 256>>>(w1, w2);
    attn_k<<<B / 4, 256, K2BYTES>>>(z, fe, ln1g, ln1b);
    ffn_mma<<<tiles, 512, SM3>>>(b1, b2, (float*)d_out);
}